// round 12
// baseline (speedup 1.0000x reference)
#include <cuda_runtime.h>
#include <cuda_bf16.h>
#include <cstdint>
#include <math.h>

// Problem constants
#define Bq 32
#define Tq 12
#define Nq 512
#define Cq 2
#define Hq 64
#define Kq 3
#define Pq 66            // C + H
#define NCOLS (Bq*Pq)    // 2112 columns of Combined
#define KP  (Kq*Pq)      // 198
#define KS2 208          // sup row stride in bf16 (416 B, 16B aligned)
#define OUTG (2*Hq)      // 128
#define NROWS (Bq*Nq)    // 16384

// ---------------- device state (no allocations allowed) ----------------
__device__ float g_h[Bq*Nq*Hq];                 // hidden state fp32
__device__ float g_z[Bq*Nq*Hq];                 // gate z
__device__ __nv_bfloat16 g_gHi[Kq*Nq*Nq];       // G split hi [k][n][j]
__device__ __nv_bfloat16 g_gLo[Kq*Nq*Nq];       // G split lo
__device__ __nv_bfloat16 g_ctHi[NCOLS*Nq];      // Combined^T hi [col][j]
__device__ __nv_bfloat16 g_ctLo[NCOLS*Nq];      // Combined^T lo
__device__ __nv_bfloat16 g_supHi[NROWS*KS2];    // sup hi [row][k] (pad cols stay 0)
__device__ __nv_bfloat16 g_supLo[NROWS*KS2];    // sup lo
__device__ __nv_bfloat16 g_WtgHi[OUTG*KS2];     // W_gate^T hi [o][k], zero-padded
__device__ __nv_bfloat16 g_WtgLo[OUTG*KS2];
__device__ __nv_bfloat16 g_WtuHi[Hq*KS2];       // W_update^T hi
__device__ __nv_bfloat16 g_WtuLo[Hq*KS2];

__device__ __forceinline__ void split_bf16(float v, __nv_bfloat16& hi, __nv_bfloat16& lo) {
    hi = __float2bfloat16(v);
    lo = __float2bfloat16(v - __bfloat162float(hi));
}

// ---------------- prep: split G; build transposed split W ----------------
__global__ void prep_g_kernel(const float* __restrict__ G) {
    int idx = blockIdx.x * blockDim.x + threadIdx.x;
    if (idx >= Kq*Nq*Nq) return;
    __nv_bfloat16 hi, lo;
    split_bf16(G[idx], hi, lo);
    g_gHi[idx] = hi;
    g_gLo[idx] = lo;
}

__global__ void prep_w_kernel(const float* __restrict__ Wg, const float* __restrict__ Wu) {
    int idx = blockIdx.x * blockDim.x + threadIdx.x;
    if (idx < OUTG*KS2) {
        int o = idx / KS2, k = idx % KS2;
        float v = (k < KP) ? Wg[k*OUTG + o] : 0.0f;
        __nv_bfloat16 hi, lo; split_bf16(v, hi, lo);
        g_WtgHi[idx] = hi; g_WtgLo[idx] = lo;
    } else if (idx < OUTG*KS2 + Hq*KS2) {
        int q = idx - OUTG*KS2;
        int o = q / KS2, k = q % KS2;
        float v = (k < KP) ? Wu[k*Hq + o] : 0.0f;
        __nv_bfloat16 hi, lo; split_bf16(v, hi, lo);
        g_WtuHi[q] = hi; g_WtuLo[q] = lo;
    }
}

// ---------------- init / set_x (t = 0 only; later t fused in gemm2m) ----------------
__global__ void init_kernel(const float* __restrict__ init_h) {
    int idx = blockIdx.x * blockDim.x + threadIdx.x;
    if (idx >= Bq*Nq*Hq) return;
    float v = init_h[idx];
    g_h[idx] = v;
    int hid = idx % Hq;
    int row = idx / Hq;
    int b = row / Nq;
    int n = row % Nq;
    __nv_bfloat16 hi, lo; split_bf16(v, hi, lo);
    int ct = (b*Pq + Cq + hid)*Nq + n;
    g_ctHi[ct] = hi; g_ctLo[ct] = lo;
}

__global__ void set_x_kernel(const float* __restrict__ x_seq, int t) {
    int idx = blockIdx.x * blockDim.x + threadIdx.x;
    if (idx >= Bq*Nq*Cq) return;
    int p = idx % Cq;
    int rest = idx / Cq;
    int n = rest % Nq;
    int b = rest / Nq;
    float v = x_seq[((b*Tq + t)*Nq + n)*Cq + p];
    __nv_bfloat16 hi, lo; split_bf16(v, hi, lo);
    int ct = (b*Pq + p)*Nq + n;
    g_ctHi[ct] = hi; g_ctLo[ct] = lo;
}

// ---------------- shared mma helpers ----------------
__device__ __forceinline__ void ldm_x4(uint32_t* r, uint32_t addr) {
    asm volatile("ldmatrix.sync.aligned.m8n8.x4.shared.b16 {%0,%1,%2,%3}, [%4];"
                 : "=r"(r[0]), "=r"(r[1]), "=r"(r[2]), "=r"(r[3]) : "r"(addr));
}
__device__ __forceinline__ void mma_bf16(float* c, const uint32_t* a, const uint32_t* b) {
    asm volatile("mma.sync.aligned.m16n8k16.row.col.f32.bf16.bf16.f32 "
                 "{%0,%1,%2,%3}, {%4,%5,%6,%7}, {%8,%9}, {%0,%1,%2,%3};"
                 : "+f"(c[0]), "+f"(c[1]), "+f"(c[2]), "+f"(c[3])
                 : "r"(a[0]), "r"(a[1]), "r"(a[2]), "r"(a[3]), "r"(b[0]), "r"(b[1]));
}
__device__ __forceinline__ uint32_t smem_u32(const void* p) {
    uint32_t a;
    asm("{ .reg .u64 t; cvta.to.shared.u64 t, %1; cvt.u32.u64 %0, t; }" : "=r"(a) : "l"(p));
    return a;
}
__device__ __forceinline__ void cp16(uint32_t dst, const void* src) {
    asm volatile("cp.async.cg.shared.global [%0], [%1], 16;" :: "r"(dst), "l"(src));
}
#define CP_COMMIT() asm volatile("cp.async.commit_group;" ::: "memory")
#define CP_WAIT2()  asm volatile("cp.async.wait_group 2;" ::: "memory")
#define CP_WAIT1()  asm volatile("cp.async.wait_group 1;" ::: "memory")
#define CP_WAIT0()  asm volatile("cp.async.wait_group 0;" ::: "memory")

// ---------------------------------------------------------------------------
// GEMM1: Sup = G[k] @ Comb, split-bf16 3-pass.
// 4-stage cp.async pipeline, k-chunk 16, prefetch depth 2, ONE sync/iter.
// CTA tile 128x96, grid (22,4,3), 256 threads. Row stride 48 B.
// Epilogue: fp32 smem staging, coalesced bf16 hi/lo store.
// ---------------------------------------------------------------------------
#define ROWB1 48
#define S_AHI 0
#define S_ALO 6144            // 128*48
#define S_BHI 12288
#define S_BLO 16896           // + 96*48
#define STG1  21504
#define SMEM_G1 (4*STG1)      // 86016; epilogue needs 128*97*4 = 49664 <= this

__global__ __launch_bounds__(256) void gemm1_mma_kernel() {
    extern __shared__ char smg[];
    const int kk = blockIdx.z;
    const int bm = blockIdx.y;
    const int bn = blockIdx.x;
    const int tid  = threadIdx.x;
    const int wid  = tid >> 5;
    const int lane = tid & 31;
    const int wm = wid & 3;
    const int wn = wid >> 2;
    const uint32_t sm0 = smem_u32(smg);

    const __nv_bfloat16* Ahi0 = g_gHi + kk*Nq*Nq + bm*128*Nq;
    const __nv_bfloat16* Alo0 = g_gLo + kk*Nq*Nq + bm*128*Nq;
    const __nv_bfloat16* Bhi0 = g_ctHi + bn*96*Nq;
    const __nv_bfloat16* Blo0 = g_ctLo + bn*96*Nq;

    const int rS = tid >> 1;          // A: 0..127; B: 0..95 (tid<192)
    const int hS = tid & 1;

    float acc[2][6][4];
    #pragma unroll
    for (int i = 0; i < 2; i++)
        #pragma unroll
        for (int j = 0; j < 6; j++)
            #pragma unroll
            for (int r = 0; r < 4; r++) acc[i][j][r] = 0.0f;

    const uint32_t aOff = (uint32_t)((lane & 15) * ROWB1 + (lane >> 4) * 16);
    const uint32_t bOff = (uint32_t)(((lane & 7) + ((lane >> 4) << 3)) * ROWB1
                                     + (((lane >> 3) & 1) * 16));

    // prefetch chunks 0, 1
    #pragma unroll
    for (int pc = 0; pc < 2; pc++) {
        const uint32_t base = sm0 + pc*STG1;
        const int kt = pc * 16;
        cp16(base + S_AHI + rS*ROWB1 + hS*16, Ahi0 + rS*Nq + kt + hS*8);
        cp16(base + S_ALO + rS*ROWB1 + hS*16, Alo0 + rS*Nq + kt + hS*8);
        if (tid < 192) {
            cp16(base + S_BHI + rS*ROWB1 + hS*16, Bhi0 + rS*Nq + kt + hS*8);
            cp16(base + S_BLO + rS*ROWB1 + hS*16, Blo0 + rS*Nq + kt + hS*8);
        }
        CP_COMMIT();
    }

    for (int c = 0; c < 32; c++) {
        if (c < 30) {
            const uint32_t base = sm0 + ((c + 2) & 3)*STG1;
            const int kt = (c + 2) * 16;
            cp16(base + S_AHI + rS*ROWB1 + hS*16, Ahi0 + rS*Nq + kt + hS*8);
            cp16(base + S_ALO + rS*ROWB1 + hS*16, Alo0 + rS*Nq + kt + hS*8);
            if (tid < 192) {
                cp16(base + S_BHI + rS*ROWB1 + hS*16, Bhi0 + rS*Nq + kt + hS*8);
                cp16(base + S_BLO + rS*ROWB1 + hS*16, Blo0 + rS*Nq + kt + hS*8);
            }
            CP_COMMIT();
            CP_WAIT2();
        } else if (c == 30) {
            CP_WAIT1();
        } else {
            CP_WAIT0();
        }
        __syncthreads();   // single barrier per iteration (4-stage, depth-2 safe)

        const uint32_t base = sm0 + (c & 3)*STG1;
        uint32_t fAhi[2][4], fAlo[2][4], fB[3][4];

        #pragma unroll
        for (int mf = 0; mf < 2; mf++)
            ldm_x4(fAhi[mf], base + S_AHI + (wm*32 + mf*16)*ROWB1 + aOff);
        #pragma unroll
        for (int q = 0; q < 3; q++)
            ldm_x4(fB[q], base + S_BHI + (wn*48 + q*16)*ROWB1 + bOff);
        #pragma unroll
        for (int mf = 0; mf < 2; mf++)
            #pragma unroll
            for (int q = 0; q < 3; q++) {
                mma_bf16(acc[mf][2*q+0], fAhi[mf], &fB[q][0]);
                mma_bf16(acc[mf][2*q+1], fAhi[mf], &fB[q][2]);
            }

        #pragma unroll
        for (int mf = 0; mf < 2; mf++)
            ldm_x4(fAlo[mf], base + S_ALO + (wm*32 + mf*16)*ROWB1 + aOff);
        #pragma unroll
        for (int mf = 0; mf < 2; mf++)
            #pragma unroll
            for (int q = 0; q < 3; q++) {
                mma_bf16(acc[mf][2*q+0], fAlo[mf], &fB[q][0]);
                mma_bf16(acc[mf][2*q+1], fAlo[mf], &fB[q][2]);
            }

        #pragma unroll
        for (int q = 0; q < 3; q++)
            ldm_x4(fB[q], base + S_BLO + (wn*48 + q*16)*ROWB1 + bOff);
        #pragma unroll
        for (int mf = 0; mf < 2; mf++)
            #pragma unroll
            for (int q = 0; q < 3; q++) {
                mma_bf16(acc[mf][2*q+0], fAhi[mf], &fB[q][0]);
                mma_bf16(acc[mf][2*q+1], fAhi[mf], &fB[q][2]);
            }
    }
    __syncthreads();   // pipeline buffers dead; reuse smem for epilogue

    // Epilogue: stage fp32 tile (stride 97), coalesced split-store
    float* fs = (float*)smg;
    const int quad = lane >> 2;
    const int tq   = lane & 3;
    #pragma unroll
    for (int mf = 0; mf < 2; mf++)
        #pragma unroll
        for (int nf = 0; nf < 6; nf++)
            #pragma unroll
            for (int r = 0; r < 4; r++) {
                int m = wm*32 + mf*16 + ((r >> 1) << 3) + quad;
                int c = wn*48 + nf*8 + tq*2 + (r & 1);
                fs[m*97 + c] = acc[mf][nf][r];
            }
    __syncthreads();
    for (int idx = tid; idx < 128*96; idx += 256) {
        int row = idx / 96;
        int c   = idx - row*96;
        float v = fs[row*97 + c];
        int col = bn*96 + c;
        int b = col / Pq;
        int p = col - b*Pq;
        __nv_bfloat16 hi, lo; split_bf16(v, hi, lo);
        int o = (b*Nq + bm*128 + row)*KS2 + kk*Pq + p;
        g_supHi[o] = hi;
        g_supLo[o] = lo;
    }
}

// ---------------------------------------------------------------------------
// GEMM2 via mma.sync, split-bf16 3-pass, cp.async double-buffered.
// Update variant also prefills next step's x columns of combT (set_x fused).
// ---------------------------------------------------------------------------
#define RB2 48

template<int OUT, bool GATE>
__global__ __launch_bounds__(256) void gemm2m_kernel(const float* __restrict__ bias,
                                                     float* __restrict__ out,
                                                     const float* __restrict__ x_seq,
                                                     int t, int is_last) {
    constexpr int NWN = OUT/64;
    constexpr int NWM = 8/NWN;
    constexpr int MT  = 128/NWM;
    constexpr int MF  = MT/16;
    constexpr int OFF2_ALO = 128*RB2;
    constexpr int OFF2_WHI = 2*128*RB2;
    constexpr int OFF2_WLO = 2*128*RB2 + OUT*RB2;
    constexpr int STG2     = 2*128*RB2 + 2*OUT*RB2;
    constexpr int SW       = OUT + 1;

    extern __shared__ char smg[];

    const int bm = blockIdx.x;
    const int tid  = threadIdx.x;
    const int wid  = tid >> 5;
    const int lane = tid & 31;
    const int wm = wid % NWM;
    const int wn = wid / NWM;
    const uint32_t sm0 = smem_u32(smg);

    const __nv_bfloat16* WtHi = GATE ? g_WtgHi : g_WtuHi;
    const __nv_bfloat16* WtLo = GATE ? g_WtgLo : g_WtuLo;
    const __nv_bfloat16* AHi0 = g_supHi + (size_t)bm*128*KS2;
    const __nv_bfloat16* ALo0 = g_supLo + (size_t)bm*128*KS2;

    const int rA = tid >> 1, hA = tid & 1;

    float acc[MF][8][4];
    #pragma unroll
    for (int mf = 0; mf < MF; mf++)
        #pragma unroll
        for (int nf = 0; nf < 8; nf++)
            #pragma unroll
            for (int r = 0; r < 4; r++)
                acc[mf][nf][r] = bias[wn*64 + nf*8 + (lane & 3)*2 + (r & 1)];

    const uint32_t aOff = (uint32_t)((lane & 15) * RB2 + (lane >> 4) * 16);
    const uint32_t bOff = (uint32_t)(((lane & 7) + ((lane >> 4) << 3)) * RB2
                                     + (((lane >> 3) & 1) * 16));

    {   // prefetch chunk 0
        const uint32_t base = sm0;
        cp16(base + 0        + rA*RB2 + hA*16, AHi0 + rA*KS2 + hA*8);
        cp16(base + OFF2_ALO + rA*RB2 + hA*16, ALo0 + rA*KS2 + hA*8);
        if (OUT == 128) {
            cp16(base + OFF2_WHI + rA*RB2 + hA*16, WtHi + rA*KS2 + hA*8);
            cp16(base + OFF2_WLO + rA*RB2 + hA*16, WtLo + rA*KS2 + hA*8);
        } else if (tid < 128) {
            cp16(base + OFF2_WHI + rA*RB2 + hA*16, WtHi + rA*KS2 + hA*8);
            cp16(base + OFF2_WLO + rA*RB2 + hA*16, WtLo + rA*KS2 + hA*8);
        }
        CP_COMMIT();
    }

    for (int c = 0; c < 13; c++) {
        if (c < 12) {
            const uint32_t base = sm0 + ((c + 1) & 1) * STG2;
            const int kt = (c + 1) * 16;
            cp16(base + 0        + rA*RB2 + hA*16, AHi0 + rA*KS2 + kt + hA*8);
            cp16(base + OFF2_ALO + rA*RB2 + hA*16, ALo0 + rA*KS2 + kt + hA*8);
            if (OUT == 128) {
                cp16(base + OFF2_WHI + rA*RB2 + hA*16, WtHi + rA*KS2 + kt + hA*8);
                cp16(base + OFF2_WLO + rA*RB2 + hA*16, WtLo + rA*KS2 + kt + hA*8);
            } else if (tid < 128) {
                cp16(base + OFF2_WHI + rA*RB2 + hA*16, WtHi + rA*KS2 + kt + hA*8);
                cp16(base + OFF2_WLO + rA*RB2 + hA*16, WtLo + rA*KS2 + kt + hA*8);
            }
            CP_COMMIT();
            CP_WAIT1();
        } else {
            CP_WAIT0();
        }
        __syncthreads();

        const uint32_t base = sm0 + (c & 1) * STG2;
        uint32_t fAhi[MF][4], fAlo[MF][4], fW[4][4];

        #pragma unroll
        for (int mf = 0; mf < MF; mf++)
            ldm_x4(fAhi[mf], base + 0 + (wm*MT + mf*16)*RB2 + aOff);
        #pragma unroll
        for (int q = 0; q < 4; q++)
            ldm_x4(fW[q], base + OFF2_WHI + (wn*64 + q*16)*RB2 + bOff);
        #pragma unroll
        for (int mf = 0; mf < MF; mf++)
            #pragma unroll
            for (int q = 0; q < 4; q++) {
                mma_bf16(acc[mf][2*q+0], fAhi[mf], &fW[q][0]);
                mma_bf16(acc[mf][2*q+1], fAhi[mf], &fW[q][2]);
            }

        #pragma unroll
        for (int mf = 0; mf < MF; mf++)
            ldm_x4(fAlo[mf], base + OFF2_ALO + (wm*MT + mf*16)*RB2 + aOff);
        #pragma unroll
        for (int mf = 0; mf < MF; mf++)
            #pragma unroll
            for (int q = 0; q < 4; q++) {
                mma_bf16(acc[mf][2*q+0], fAlo[mf], &fW[q][0]);
                mma_bf16(acc[mf][2*q+1], fAlo[mf], &fW[q][2]);
            }

        #pragma unroll
        for (int q = 0; q < 4; q++)
            ldm_x4(fW[q], base + OFF2_WLO + (wn*64 + q*16)*RB2 + bOff);
        #pragma unroll
        for (int mf = 0; mf < MF; mf++)
            #pragma unroll
            for (int q = 0; q < 4; q++) {
                mma_bf16(acc[mf][2*q+0], fAhi[mf], &fW[q][0]);
                mma_bf16(acc[mf][2*q+1], fAhi[mf], &fW[q][2]);
            }
        __syncthreads();
    }

    // ---- Epilogue: stage acc in smem fp32 [128][SW], then coalesced passes.
    float* fs = (float*)smg;
    const int quad = lane >> 2;
    const int tq   = lane & 3;
    #pragma unroll
    for (int mf = 0; mf < MF; mf++)
        #pragma unroll
        for (int nf = 0; nf < 8; nf++)
            #pragma unroll
            for (int r = 0; r < 4; r++) {
                int rl = wm*MT + mf*16 + ((r >> 1) << 3) + quad;
                int o  = wn*64 + nf*8 + tq*2 + (r & 1);
                fs[rl*SW + o] = acc[mf][nf][r];
            }
    __syncthreads();

    if (GATE) {
        for (int idx = tid; idx < 128*OUT; idx += 256) {
            int rl = idx >> 7;
            int o  = idx & 127;
            int row = bm*128 + rl;
            float zv = 1.0f / (1.0f + __expf(-fs[rl*SW + o]));
            if (o < Hq) {
                g_z[row*Hq + o] = zv;
            } else {
                fs[rl*SW + o] = zv * g_h[row*Hq + (o - Hq)];
            }
        }
        __syncthreads();
        for (int idx = tid; idx < Hq*128; idx += 256) {
            int hid = idx >> 7;
            int rl  = idx & 127;
            float rh = fs[rl*SW + Hq + hid];
            __nv_bfloat16 hi, lo; split_bf16(rh, hi, lo);
            int row = bm*128 + rl;
            int b = row >> 9;
            int n = row & (Nq - 1);
            int ct = (b*Pq + Cq + hid)*Nq + n;
            g_ctHi[ct] = hi; g_ctLo[ct] = lo;
        }
    } else {
        for (int idx = tid; idx < 128*OUT; idx += 256) {
            int rl = idx >> 6;
            int o  = idx & 63;
            int row = bm*128 + rl;
            float hc   = tanhf(fs[rl*SW + o]);
            float zv   = g_z[row*Hq + o];
            float hold = g_h[row*Hq + o];
            float hnew = (1.0f - zv)*hold + zv*hc;
            g_h[row*Hq + o] = hnew;
            if (is_last) out[row*Hq + o] = hnew;
            fs[rl*SW + o] = hnew;
        }
        __syncthreads();
        for (int idx = tid; idx < Hq*128; idx += 256) {
            int o  = idx >> 7;
            int rl = idx & 127;
            float hnew = fs[rl*SW + o];
            __nv_bfloat16 hi, lo; split_bf16(hnew, hi, lo);
            int row = bm*128 + rl;
            int b = row >> 9;
            int n = row & (Nq - 1);
            int ct = (b*Pq + Cq + o)*Nq + n;
            g_ctHi[ct] = hi; g_ctLo[ct] = lo;
        }
        // fused set_x for step t+1 (256 elems: p in {0,1} x 128 rows)
        if (!is_last) {
            int p  = tid >> 7;
            int rl = tid & 127;
            int row = bm*128 + rl;
            int b = row >> 9;
            int n = row & (Nq - 1);
            float v = x_seq[((b*Tq + (t + 1))*Nq + n)*Cq + p];
            __nv_bfloat16 hi, lo; split_bf16(v, hi, lo);
            int ct = (b*Pq + p)*Nq + n;
            g_ctHi[ct] = hi; g_ctLo[ct] = lo;
        }
    }
}

// Host-side dynamic smem sizes for gemm2m
#define STG2_GATE (2*128*RB2 + 2*OUTG*RB2)          // 24576
#define STG2_UPD  (2*128*RB2 + 2*Hq*RB2)            // 18432
#define SM2_GATE  ((2*STG2_GATE) > (128*(OUTG+1)*4) ? (2*STG2_GATE) : (128*(OUTG+1)*4))
#define SM2_UPD   ((2*STG2_UPD)  > (128*(Hq+1)*4)  ? (2*STG2_UPD)  : (128*(Hq+1)*4))

// ---------------------------------------------------------------------------
// kernel_launch
// Inputs: G, x_seq, init_h, W_gate, b_gate, W_update, b_update
// ---------------------------------------------------------------------------
extern "C" void kernel_launch(void* const* d_in, const int* in_sizes, int n_in,
                              void* d_out, int out_size) {
    const float* G        = (const float*)d_in[0];
    const float* x_seq    = (const float*)d_in[1];
    const float* init_h   = (const float*)d_in[2];
    const float* W_gate   = (const float*)d_in[3];
    const float* b_gate   = (const float*)d_in[4];
    const float* W_update = (const float*)d_in[5];
    const float* b_update = (const float*)d_in[6];
    float* out = (float*)d_out;

    cudaFuncSetAttribute(gemm1_mma_kernel,
                         cudaFuncAttributeMaxDynamicSharedMemorySize, SMEM_G1);
    cudaFuncSetAttribute(gemm2m_kernel<OUTG, true>,
                         cudaFuncAttributeMaxDynamicSharedMemorySize, SM2_GATE);
    cudaFuncSetAttribute(gemm2m_kernel<Hq, false>,
                         cudaFuncAttributeMaxDynamicSharedMemorySize, SM2_UPD);

    prep_g_kernel<<<(Kq*Nq*Nq + 255)/256, 256>>>(G);
    prep_w_kernel<<<((OUTG + Hq)*KS2 + 255)/256, 256>>>(W_gate, W_update);
    init_kernel<<<(Bq*Nq*Hq + 255)/256, 256>>>(init_h);
    set_x_kernel<<<(Bq*Nq*Cq + 255)/256, 256>>>(x_seq, 0);   // t = 0 only

    dim3 g1(NCOLS/96, Nq/128, Kq);   // (22, 4, 3)
    for (int t = 0; t < Tq; t++) {
        gemm1_mma_kernel<<<g1, 256, SMEM_G1>>>();
        gemm2m_kernel<OUTG, true><<<NROWS/128, 256, SM2_GATE>>>(b_gate, out, x_seq, t, 0);
        gemm1_mma_kernel<<<g1, 256, SMEM_G1>>>();
        gemm2m_kernel<Hq, false><<<NROWS/128, 256, SM2_UPD>>>(b_update, out, x_seq, t, t == Tq - 1);
    }
}

// round 13
// speedup vs baseline: 1.0149x; 1.0149x over previous
#include <cuda_runtime.h>
#include <cuda_bf16.h>
#include <cstdint>
#include <math.h>

// Problem constants
#define Bq 32
#define Tq 12
#define Nq 512
#define Cq 2
#define Hq 64
#define Kq 3
#define Pq 66            // C + H
#define NCOLS (Bq*Pq)    // 2112 columns of Combined
#define KP  (Kq*Pq)      // 198
#define KS2 208          // sup row stride in bf16 (416 B, 16B aligned)
#define OUTG (2*Hq)      // 128
#define NROWS (Bq*Nq)    // 16384

// ---------------- device state (no allocations allowed) ----------------
__device__ float g_h[Bq*Nq*Hq];                 // hidden state fp32
__device__ float g_z[Bq*Nq*Hq];                 // gate z
__device__ __nv_bfloat16 g_gHi[Kq*Nq*Nq];       // G split hi [k][n][j]
__device__ __nv_bfloat16 g_gLo[Kq*Nq*Nq];       // G split lo
__device__ __nv_bfloat16 g_ctHi[NCOLS*Nq];      // Combined^T hi [col][j]
__device__ __nv_bfloat16 g_ctLo[NCOLS*Nq];      // Combined^T lo
__device__ __nv_bfloat16 g_supHi[NROWS*KS2];    // sup hi [row][k] (pad cols stay 0)
__device__ __nv_bfloat16 g_supLo[NROWS*KS2];    // sup lo
__device__ __nv_bfloat16 g_WtgHi[OUTG*KS2];     // W_gate^T hi [o][k], zero-padded
__device__ __nv_bfloat16 g_WtgLo[OUTG*KS2];
__device__ __nv_bfloat16 g_WtuHi[Hq*KS2];       // W_update^T hi
__device__ __nv_bfloat16 g_WtuLo[Hq*KS2];

__device__ __forceinline__ void split_bf16(float v, __nv_bfloat16& hi, __nv_bfloat16& lo) {
    hi = __float2bfloat16(v);
    lo = __float2bfloat16(v - __bfloat162float(hi));
}

// ---------------- prep: split G; build transposed split W ----------------
__global__ void prep_g_kernel(const float* __restrict__ G) {
    int idx = blockIdx.x * blockDim.x + threadIdx.x;
    if (idx >= Kq*Nq*Nq) return;
    __nv_bfloat16 hi, lo;
    split_bf16(G[idx], hi, lo);
    g_gHi[idx] = hi;
    g_gLo[idx] = lo;
}

__global__ void prep_w_kernel(const float* __restrict__ Wg, const float* __restrict__ Wu) {
    int idx = blockIdx.x * blockDim.x + threadIdx.x;
    if (idx < OUTG*KS2) {
        int o = idx / KS2, k = idx % KS2;
        float v = (k < KP) ? Wg[k*OUTG + o] : 0.0f;
        __nv_bfloat16 hi, lo; split_bf16(v, hi, lo);
        g_WtgHi[idx] = hi; g_WtgLo[idx] = lo;
    } else if (idx < OUTG*KS2 + Hq*KS2) {
        int q = idx - OUTG*KS2;
        int o = q / KS2, k = q % KS2;
        float v = (k < KP) ? Wu[k*Hq + o] : 0.0f;
        __nv_bfloat16 hi, lo; split_bf16(v, hi, lo);
        g_WtuHi[q] = hi; g_WtuLo[q] = lo;
    }
}

// ---------------- init / set_x (t = 0 only; later t fused in gemm2m) ----------------
__global__ void init_kernel(const float* __restrict__ init_h) {
    int idx = blockIdx.x * blockDim.x + threadIdx.x;
    if (idx >= Bq*Nq*Hq) return;
    float v = init_h[idx];
    g_h[idx] = v;
    int hid = idx % Hq;
    int row = idx / Hq;
    int b = row / Nq;
    int n = row % Nq;
    __nv_bfloat16 hi, lo; split_bf16(v, hi, lo);
    int ct = (b*Pq + Cq + hid)*Nq + n;
    g_ctHi[ct] = hi; g_ctLo[ct] = lo;
}

__global__ void set_x_kernel(const float* __restrict__ x_seq, int t) {
    int idx = blockIdx.x * blockDim.x + threadIdx.x;
    if (idx >= Bq*Nq*Cq) return;
    int p = idx % Cq;
    int rest = idx / Cq;
    int n = rest % Nq;
    int b = rest / Nq;
    float v = x_seq[((b*Tq + t)*Nq + n)*Cq + p];
    __nv_bfloat16 hi, lo; split_bf16(v, hi, lo);
    int ct = (b*Pq + p)*Nq + n;
    g_ctHi[ct] = hi; g_ctLo[ct] = lo;
}

// ---------------- shared mma helpers ----------------
__device__ __forceinline__ void ldm_x4(uint32_t* r, uint32_t addr) {
    asm volatile("ldmatrix.sync.aligned.m8n8.x4.shared.b16 {%0,%1,%2,%3}, [%4];"
                 : "=r"(r[0]), "=r"(r[1]), "=r"(r[2]), "=r"(r[3]) : "r"(addr));
}
__device__ __forceinline__ void mma_bf16(float* c, const uint32_t* a, const uint32_t* b) {
    asm volatile("mma.sync.aligned.m16n8k16.row.col.f32.bf16.bf16.f32 "
                 "{%0,%1,%2,%3}, {%4,%5,%6,%7}, {%8,%9}, {%0,%1,%2,%3};"
                 : "+f"(c[0]), "+f"(c[1]), "+f"(c[2]), "+f"(c[3])
                 : "r"(a[0]), "r"(a[1]), "r"(a[2]), "r"(a[3]), "r"(b[0]), "r"(b[1]));
}
__device__ __forceinline__ uint32_t smem_u32(const void* p) {
    uint32_t a;
    asm("{ .reg .u64 t; cvta.to.shared.u64 t, %1; cvt.u32.u64 %0, t; }" : "=r"(a) : "l"(p));
    return a;
}
__device__ __forceinline__ void cp16(uint32_t dst, const void* src) {
    asm volatile("cp.async.cg.shared.global [%0], [%1], 16;" :: "r"(dst), "l"(src));
}
#define CP_COMMIT() asm volatile("cp.async.commit_group;" ::: "memory")
#define CP_WAIT1()  asm volatile("cp.async.wait_group 1;" ::: "memory")
#define CP_WAIT0()  asm volatile("cp.async.wait_group 0;" ::: "memory")

// ---------------------------------------------------------------------------
// GEMM1: Sup = G[k] @ Comb, split-bf16 3-pass, cp.async double-buffered.
// 2-stage pipeline, K-chunk 32 (round-11 measured-best config).
// CTA tile 128x96, grid (22,4,3), 256 threads. Row stride 80 B.
// Epilogue: fp32 smem staging, coalesced bf16 hi/lo store.
// ---------------------------------------------------------------------------
#define ROWB 80
#define OFF_AHI 0
#define OFF_ALO 10240
#define OFF_BHI 20480
#define OFF_BLO 28160
#define STGSZ   35840
#define SMEM_G1 (2*STGSZ)   // 71680 >= 128*97*4 epilogue buffer

__global__ __launch_bounds__(256) void gemm1_mma_kernel() {
    extern __shared__ char smg[];
    const int kk = blockIdx.z;
    const int bm = blockIdx.y;
    const int bn = blockIdx.x;
    const int tid  = threadIdx.x;
    const int wid  = tid >> 5;
    const int lane = tid & 31;
    const int wm = wid & 3;
    const int wn = wid >> 2;
    const uint32_t sm0 = smem_u32(smg);

    const __nv_bfloat16* Ahi0 = g_gHi + kk*Nq*Nq + bm*128*Nq;
    const __nv_bfloat16* Alo0 = g_gLo + kk*Nq*Nq + bm*128*Nq;
    const __nv_bfloat16* Bhi0 = g_ctHi + bn*96*Nq;
    const __nv_bfloat16* Blo0 = g_ctLo + bn*96*Nq;

    const int rA0 = tid >> 2,          qA0 = (tid & 3);
    const int rA1 = (tid + 256) >> 2,  qA1 = (tid & 3);
    const int rB0 = tid >> 2,          qB0 = (tid & 3);
    const int rB1 = (tid + 256) >> 2,  qB1 = (tid & 3);

    float acc[2][6][4];
    #pragma unroll
    for (int i = 0; i < 2; i++)
        #pragma unroll
        for (int j = 0; j < 6; j++)
            #pragma unroll
            for (int r = 0; r < 4; r++) acc[i][j][r] = 0.0f;

    const uint32_t aOff = (uint32_t)((lane & 15) * ROWB + (lane >> 4) * 16);
    const uint32_t bOff = (uint32_t)(((lane & 7) + ((lane >> 4) << 3)) * ROWB
                                     + (((lane >> 3) & 1) * 16));

    {   // prefetch chunk 0
        const uint32_t base = sm0;
        cp16(base + OFF_AHI + rA0*ROWB + qA0*16, Ahi0 + rA0*Nq + qA0*8);
        cp16(base + OFF_ALO + rA0*ROWB + qA0*16, Alo0 + rA0*Nq + qA0*8);
        cp16(base + OFF_AHI + rA1*ROWB + qA1*16, Ahi0 + rA1*Nq + qA1*8);
        cp16(base + OFF_ALO + rA1*ROWB + qA1*16, Alo0 + rA1*Nq + qA1*8);
        cp16(base + OFF_BHI + rB0*ROWB + qB0*16, Bhi0 + rB0*Nq + qB0*8);
        cp16(base + OFF_BLO + rB0*ROWB + qB0*16, Blo0 + rB0*Nq + qB0*8);
        if (tid < 128) {
            cp16(base + OFF_BHI + rB1*ROWB + qB1*16, Bhi0 + rB1*Nq + qB1*8);
            cp16(base + OFF_BLO + rB1*ROWB + qB1*16, Blo0 + rB1*Nq + qB1*8);
        }
        CP_COMMIT();
    }

    for (int c = 0; c < 16; c++) {
        if (c < 15) {
            const uint32_t base = sm0 + ((c + 1) & 1) * STGSZ;
            const int kt = (c + 1) * 32;
            cp16(base + OFF_AHI + rA0*ROWB + qA0*16, Ahi0 + rA0*Nq + kt + qA0*8);
            cp16(base + OFF_ALO + rA0*ROWB + qA0*16, Alo0 + rA0*Nq + kt + qA0*8);
            cp16(base + OFF_AHI + rA1*ROWB + qA1*16, Ahi0 + rA1*Nq + kt + qA1*8);
            cp16(base + OFF_ALO + rA1*ROWB + qA1*16, Alo0 + rA1*Nq + kt + qA1*8);
            cp16(base + OFF_BHI + rB0*ROWB + qB0*16, Bhi0 + rB0*Nq + kt + qB0*8);
            cp16(base + OFF_BLO + rB0*ROWB + qB0*16, Blo0 + rB0*Nq + kt + qB0*8);
            if (tid < 128) {
                cp16(base + OFF_BHI + rB1*ROWB + qB1*16, Bhi0 + rB1*Nq + kt + qB1*8);
                cp16(base + OFF_BLO + rB1*ROWB + qB1*16, Blo0 + rB1*Nq + kt + qB1*8);
            }
            CP_COMMIT();
            CP_WAIT1();
        } else {
            CP_WAIT0();
        }
        __syncthreads();

        const uint32_t base = sm0 + (c & 1) * STGSZ;
        const uint32_t uAhi = base + OFF_AHI;
        const uint32_t uAlo = base + OFF_ALO;
        const uint32_t uBhi = base + OFF_BHI;
        const uint32_t uBlo = base + OFF_BLO;

        #pragma unroll
        for (int ks = 0; ks < 2; ks++) {
            const uint32_t kByte = (uint32_t)(ks * 32);
            uint32_t fAhi[2][4], fAlo[2][4], fB[3][4];

            #pragma unroll
            for (int mf = 0; mf < 2; mf++)
                ldm_x4(fAhi[mf], uAhi + (wm*32 + mf*16)*ROWB + aOff + kByte);
            #pragma unroll
            for (int q = 0; q < 3; q++)
                ldm_x4(fB[q], uBhi + (wn*48 + q*16)*ROWB + bOff + kByte);
            #pragma unroll
            for (int mf = 0; mf < 2; mf++)
                #pragma unroll
                for (int q = 0; q < 3; q++) {
                    mma_bf16(acc[mf][2*q+0], fAhi[mf], &fB[q][0]);
                    mma_bf16(acc[mf][2*q+1], fAhi[mf], &fB[q][2]);
                }

            #pragma unroll
            for (int mf = 0; mf < 2; mf++)
                ldm_x4(fAlo[mf], uAlo + (wm*32 + mf*16)*ROWB + aOff + kByte);
            #pragma unroll
            for (int mf = 0; mf < 2; mf++)
                #pragma unroll
                for (int q = 0; q < 3; q++) {
                    mma_bf16(acc[mf][2*q+0], fAlo[mf], &fB[q][0]);
                    mma_bf16(acc[mf][2*q+1], fAlo[mf], &fB[q][2]);
                }

            #pragma unroll
            for (int q = 0; q < 3; q++)
                ldm_x4(fB[q], uBlo + (wn*48 + q*16)*ROWB + bOff + kByte);
            #pragma unroll
            for (int mf = 0; mf < 2; mf++)
                #pragma unroll
                for (int q = 0; q < 3; q++) {
                    mma_bf16(acc[mf][2*q+0], fAhi[mf], &fB[q][0]);
                    mma_bf16(acc[mf][2*q+1], fAhi[mf], &fB[q][2]);
                }
        }
        __syncthreads();
    }

    // Epilogue: stage fp32 tile (stride 97), coalesced split-store
    float* fs = (float*)smg;
    const int quad = lane >> 2;
    const int tq   = lane & 3;
    #pragma unroll
    for (int mf = 0; mf < 2; mf++)
        #pragma unroll
        for (int nf = 0; nf < 6; nf++)
            #pragma unroll
            for (int r = 0; r < 4; r++) {
                int m = wm*32 + mf*16 + ((r >> 1) << 3) + quad;
                int c = wn*48 + nf*8 + tq*2 + (r & 1);
                fs[m*97 + c] = acc[mf][nf][r];
            }
    __syncthreads();
    for (int idx = tid; idx < 128*96; idx += 256) {
        int row = idx / 96;
        int c   = idx - row*96;
        float v = fs[row*97 + c];
        int col = bn*96 + c;
        int b = col / Pq;
        int p = col - b*Pq;
        __nv_bfloat16 hi, lo; split_bf16(v, hi, lo);
        int o = (b*Nq + bm*128 + row)*KS2 + kk*Pq + p;
        g_supHi[o] = hi;
        g_supLo[o] = lo;
    }
}

// ---------------------------------------------------------------------------
// GEMM2 via mma.sync, split-bf16 3-pass, cp.async double-buffered.
// Update variant also prefills next step's x columns of combT (set_x fused).
// ---------------------------------------------------------------------------
#define RB2 48

template<int OUT, bool GATE>
__global__ __launch_bounds__(256) void gemm2m_kernel(const float* __restrict__ bias,
                                                     float* __restrict__ out,
                                                     const float* __restrict__ x_seq,
                                                     int t, int is_last) {
    constexpr int NWN = OUT/64;
    constexpr int NWM = 8/NWN;
    constexpr int MT  = 128/NWM;
    constexpr int MF  = MT/16;
    constexpr int OFF2_ALO = 128*RB2;
    constexpr int OFF2_WHI = 2*128*RB2;
    constexpr int OFF2_WLO = 2*128*RB2 + OUT*RB2;
    constexpr int STG2     = 2*128*RB2 + 2*OUT*RB2;
    constexpr int SW       = OUT + 1;

    extern __shared__ char smg[];

    const int bm = blockIdx.x;
    const int tid  = threadIdx.x;
    const int wid  = tid >> 5;
    const int lane = tid & 31;
    const int wm = wid % NWM;
    const int wn = wid / NWM;
    const uint32_t sm0 = smem_u32(smg);

    const __nv_bfloat16* WtHi = GATE ? g_WtgHi : g_WtuHi;
    const __nv_bfloat16* WtLo = GATE ? g_WtgLo : g_WtuLo;
    const __nv_bfloat16* AHi0 = g_supHi + (size_t)bm*128*KS2;
    const __nv_bfloat16* ALo0 = g_supLo + (size_t)bm*128*KS2;

    const int rA = tid >> 1, hA = tid & 1;

    float acc[MF][8][4];
    #pragma unroll
    for (int mf = 0; mf < MF; mf++)
        #pragma unroll
        for (int nf = 0; nf < 8; nf++)
            #pragma unroll
            for (int r = 0; r < 4; r++)
                acc[mf][nf][r] = bias[wn*64 + nf*8 + (lane & 3)*2 + (r & 1)];

    const uint32_t aOff = (uint32_t)((lane & 15) * RB2 + (lane >> 4) * 16);
    const uint32_t bOff = (uint32_t)(((lane & 7) + ((lane >> 4) << 3)) * RB2
                                     + (((lane >> 3) & 1) * 16));

    {   // prefetch chunk 0
        const uint32_t base = sm0;
        cp16(base + 0        + rA*RB2 + hA*16, AHi0 + rA*KS2 + hA*8);
        cp16(base + OFF2_ALO + rA*RB2 + hA*16, ALo0 + rA*KS2 + hA*8);
        if (OUT == 128) {
            cp16(base + OFF2_WHI + rA*RB2 + hA*16, WtHi + rA*KS2 + hA*8);
            cp16(base + OFF2_WLO + rA*RB2 + hA*16, WtLo + rA*KS2 + hA*8);
        } else if (tid < 128) {
            cp16(base + OFF2_WHI + rA*RB2 + hA*16, WtHi + rA*KS2 + hA*8);
            cp16(base + OFF2_WLO + rA*RB2 + hA*16, WtLo + rA*KS2 + hA*8);
        }
        CP_COMMIT();
    }

    for (int c = 0; c < 13; c++) {
        if (c < 12) {
            const uint32_t base = sm0 + ((c + 1) & 1) * STG2;
            const int kt = (c + 1) * 16;
            cp16(base + 0        + rA*RB2 + hA*16, AHi0 + rA*KS2 + kt + hA*8);
            cp16(base + OFF2_ALO + rA*RB2 + hA*16, ALo0 + rA*KS2 + kt + hA*8);
            if (OUT == 128) {
                cp16(base + OFF2_WHI + rA*RB2 + hA*16, WtHi + rA*KS2 + kt + hA*8);
                cp16(base + OFF2_WLO + rA*RB2 + hA*16, WtLo + rA*KS2 + kt + hA*8);
            } else if (tid < 128) {
                cp16(base + OFF2_WHI + rA*RB2 + hA*16, WtHi + rA*KS2 + kt + hA*8);
                cp16(base + OFF2_WLO + rA*RB2 + hA*16, WtLo + rA*KS2 + kt + hA*8);
            }
            CP_COMMIT();
            CP_WAIT1();
        } else {
            CP_WAIT0();
        }
        __syncthreads();

        const uint32_t base = sm0 + (c & 1) * STG2;
        uint32_t fAhi[MF][4], fAlo[MF][4], fW[4][4];

        #pragma unroll
        for (int mf = 0; mf < MF; mf++)
            ldm_x4(fAhi[mf], base + 0 + (wm*MT + mf*16)*RB2 + aOff);
        #pragma unroll
        for (int q = 0; q < 4; q++)
            ldm_x4(fW[q], base + OFF2_WHI + (wn*64 + q*16)*RB2 + bOff);
        #pragma unroll
        for (int mf = 0; mf < MF; mf++)
            #pragma unroll
            for (int q = 0; q < 4; q++) {
                mma_bf16(acc[mf][2*q+0], fAhi[mf], &fW[q][0]);
                mma_bf16(acc[mf][2*q+1], fAhi[mf], &fW[q][2]);
            }

        #pragma unroll
        for (int mf = 0; mf < MF; mf++)
            ldm_x4(fAlo[mf], base + OFF2_ALO + (wm*MT + mf*16)*RB2 + aOff);
        #pragma unroll
        for (int mf = 0; mf < MF; mf++)
            #pragma unroll
            for (int q = 0; q < 4; q++) {
                mma_bf16(acc[mf][2*q+0], fAlo[mf], &fW[q][0]);
                mma_bf16(acc[mf][2*q+1], fAlo[mf], &fW[q][2]);
            }

        #pragma unroll
        for (int q = 0; q < 4; q++)
            ldm_x4(fW[q], base + OFF2_WLO + (wn*64 + q*16)*RB2 + bOff);
        #pragma unroll
        for (int mf = 0; mf < MF; mf++)
            #pragma unroll
            for (int q = 0; q < 4; q++) {
                mma_bf16(acc[mf][2*q+0], fAhi[mf], &fW[q][0]);
                mma_bf16(acc[mf][2*q+1], fAhi[mf], &fW[q][2]);
            }
        __syncthreads();
    }

    // ---- Epilogue: stage acc in smem fp32 [128][SW], then coalesced passes.
    float* fs = (float*)smg;
    const int quad = lane >> 2;
    const int tq   = lane & 3;
    #pragma unroll
    for (int mf = 0; mf < MF; mf++)
        #pragma unroll
        for (int nf = 0; nf < 8; nf++)
            #pragma unroll
            for (int r = 0; r < 4; r++) {
                int rl = wm*MT + mf*16 + ((r >> 1) << 3) + quad;
                int o  = wn*64 + nf*8 + tq*2 + (r & 1);
                fs[rl*SW + o] = acc[mf][nf][r];
            }
    __syncthreads();

    if (GATE) {
        for (int idx = tid; idx < 128*OUT; idx += 256) {
            int rl = idx >> 7;
            int o  = idx & 127;
            int row = bm*128 + rl;
            float zv = 1.0f / (1.0f + __expf(-fs[rl*SW + o]));
            if (o < Hq) {
                g_z[row*Hq + o] = zv;
            } else {
                fs[rl*SW + o] = zv * g_h[row*Hq + (o - Hq)];
            }
        }
        __syncthreads();
        for (int idx = tid; idx < Hq*128; idx += 256) {
            int hid = idx >> 7;
            int rl  = idx & 127;
            float rh = fs[rl*SW + Hq + hid];
            __nv_bfloat16 hi, lo; split_bf16(rh, hi, lo);
            int row = bm*128 + rl;
            int b = row >> 9;
            int n = row & (Nq - 1);
            int ct = (b*Pq + Cq + hid)*Nq + n;
            g_ctHi[ct] = hi; g_ctLo[ct] = lo;
        }
    } else {
        for (int idx = tid; idx < 128*OUT; idx += 256) {
            int rl = idx >> 6;
            int o  = idx & 63;
            int row = bm*128 + rl;
            float hc   = tanhf(fs[rl*SW + o]);
            float zv   = g_z[row*Hq + o];
            float hold = g_h[row*Hq + o];
            float hnew = (1.0f - zv)*hold + zv*hc;
            g_h[row*Hq + o] = hnew;
            if (is_last) out[row*Hq + o] = hnew;
            fs[rl*SW + o] = hnew;
        }
        __syncthreads();
        for (int idx = tid; idx < Hq*128; idx += 256) {
            int o  = idx >> 7;
            int rl = idx & 127;
            float hnew = fs[rl*SW + o];
            __nv_bfloat16 hi, lo; split_bf16(hnew, hi, lo);
            int row = bm*128 + rl;
            int b = row >> 9;
            int n = row & (Nq - 1);
            int ct = (b*Pq + Cq + o)*Nq + n;
            g_ctHi[ct] = hi; g_ctLo[ct] = lo;
        }
        // fused set_x for step t+1 (256 elems: p in {0,1} x 128 rows)
        if (!is_last) {
            int p  = tid >> 7;
            int rl = tid & 127;
            int row = bm*128 + rl;
            int b = row >> 9;
            int n = row & (Nq - 1);
            float v = x_seq[((b*Tq + (t + 1))*Nq + n)*Cq + p];
            __nv_bfloat16 hi, lo; split_bf16(v, hi, lo);
            int ct = (b*Pq + p)*Nq + n;
            g_ctHi[ct] = hi; g_ctLo[ct] = lo;
        }
    }
}

// Host-side dynamic smem sizes for gemm2m
#define STG2_GATE (2*128*RB2 + 2*OUTG*RB2)          // 24576
#define STG2_UPD  (2*128*RB2 + 2*Hq*RB2)            // 18432
#define SM2_GATE  ((2*STG2_GATE) > (128*(OUTG+1)*4) ? (2*STG2_GATE) : (128*(OUTG+1)*4))
#define SM2_UPD   ((2*STG2_UPD)  > (128*(Hq+1)*4)  ? (2*STG2_UPD)  : (128*(Hq+1)*4))

// ---------------------------------------------------------------------------
// kernel_launch
// Inputs: G, x_seq, init_h, W_gate, b_gate, W_update, b_update
// ---------------------------------------------------------------------------
extern "C" void kernel_launch(void* const* d_in, const int* in_sizes, int n_in,
                              void* d_out, int out_size) {
    const float* G        = (const float*)d_in[0];
    const float* x_seq    = (const float*)d_in[1];
    const float* init_h   = (const float*)d_in[2];
    const float* W_gate   = (const float*)d_in[3];
    const float* b_gate   = (const float*)d_in[4];
    const float* W_update = (const float*)d_in[5];
    const float* b_update = (const float*)d_in[6];
    float* out = (float*)d_out;

    cudaFuncSetAttribute(gemm1_mma_kernel,
                         cudaFuncAttributeMaxDynamicSharedMemorySize, SMEM_G1);
    cudaFuncSetAttribute(gemm2m_kernel<OUTG, true>,
                         cudaFuncAttributeMaxDynamicSharedMemorySize, SM2_GATE);
    cudaFuncSetAttribute(gemm2m_kernel<Hq, false>,
                         cudaFuncAttributeMaxDynamicSharedMemorySize, SM2_UPD);

    prep_g_kernel<<<(Kq*Nq*Nq + 255)/256, 256>>>(G);
    prep_w_kernel<<<((OUTG + Hq)*KS2 + 255)/256, 256>>>(W_gate, W_update);
    init_kernel<<<(Bq*Nq*Hq + 255)/256, 256>>>(init_h);
    set_x_kernel<<<(Bq*Nq*Cq + 255)/256, 256>>>(x_seq, 0);   // t = 0 only

    dim3 g1(NCOLS/96, Nq/128, Kq);   // (22, 4, 3)
    for (int t = 0; t < Tq; t++) {
        gemm1_mma_kernel<<<g1, 256, SMEM_G1>>>();
        gemm2m_kernel<OUTG, true><<<NROWS/128, 256, SM2_GATE>>>(b_gate, out, x_seq, t, 0);
        gemm1_mma_kernel<<<g1, 256, SMEM_G1>>>();
        gemm2m_kernel<Hq, false><<<NROWS/128, 256, SM2_UPD>>>(b_update, out, x_seq, t, t == Tq - 1);
    }
}

// round 14
// speedup vs baseline: 1.2474x; 1.2292x over previous
#include <cuda_runtime.h>
#include <cuda_fp16.h>
#include <cstdint>
#include <math.h>

// Problem constants
#define Bq 32
#define Tq 12
#define Nq 512
#define Cq 2
#define Hq 64
#define Kq 3
#define Pq 66            // C + H
#define NCOLS (Bq*Pq)    // 2112 columns of Combined
#define KP  (Kq*Pq)      // 198
#define KS2 208          // sup row stride in fp16 (416 B, 16B aligned)
#define OUTG (2*Hq)      // 128
#define NROWS (Bq*Nq)    // 16384

// ---------------- device state (no allocations allowed) ----------------
__device__ float g_h[Bq*Nq*Hq];           // hidden state fp32
__device__ float g_z[Bq*Nq*Hq];           // gate z
__device__ __half g_gHi[Kq*Nq*Nq];        // G split hi [k][n][j]
__device__ __half g_gLo[Kq*Nq*Nq];        // G split lo
__device__ __half g_ct[NCOLS*Nq];         // Combined^T fp16 [col][j]
__device__ __half g_supHi[NROWS*KS2];     // sup hi [row][k] (pad cols stay 0)
__device__ __half g_supLo[NROWS*KS2];     // sup lo
__device__ __half g_Wtg[OUTG*KS2];        // W_gate^T fp16 [o][k], zero-padded
__device__ __half g_Wtu[Hq*KS2];          // W_update^T fp16

__device__ __forceinline__ void split_fp16(float v, __half& hi, __half& lo) {
    hi = __float2half(v);
    lo = __float2half(v - __half2float(hi));
}

// ---------------- prep: split G; build transposed W ----------------
__global__ void prep_g_kernel(const float* __restrict__ G) {
    int idx = blockIdx.x * blockDim.x + threadIdx.x;
    if (idx >= Kq*Nq*Nq) return;
    __half hi, lo;
    split_fp16(G[idx], hi, lo);
    g_gHi[idx] = hi;
    g_gLo[idx] = lo;
}

__global__ void prep_w_kernel(const float* __restrict__ Wg, const float* __restrict__ Wu) {
    int idx = blockIdx.x * blockDim.x + threadIdx.x;
    if (idx < OUTG*KS2) {
        int o = idx / KS2, k = idx % KS2;
        g_Wtg[idx] = __float2half((k < KP) ? Wg[k*OUTG + o] : 0.0f);
    } else if (idx < OUTG*KS2 + Hq*KS2) {
        int q = idx - OUTG*KS2;
        int o = q / KS2, k = q % KS2;
        g_Wtu[q] = __float2half((k < KP) ? Wu[k*Hq + o] : 0.0f);
    }
}

// ---------------- init / set_x (t = 0 only; later t fused in gemm2m) ----------------
__global__ void init_kernel(const float* __restrict__ init_h) {
    int idx = blockIdx.x * blockDim.x + threadIdx.x;
    if (idx >= Bq*Nq*Hq) return;
    float v = init_h[idx];
    g_h[idx] = v;
    int hid = idx % Hq;
    int row = idx / Hq;
    int b = row / Nq;
    int n = row % Nq;
    g_ct[(b*Pq + Cq + hid)*Nq + n] = __float2half(v);
}

__global__ void set_x_kernel(const float* __restrict__ x_seq, int t) {
    int idx = blockIdx.x * blockDim.x + threadIdx.x;
    if (idx >= Bq*Nq*Cq) return;
    int p = idx % Cq;
    int rest = idx / Cq;
    int n = rest % Nq;
    int b = rest / Nq;
    g_ct[(b*Pq + p)*Nq + n] =
        __float2half(x_seq[((b*Tq + t)*Nq + n)*Cq + p]);
}

// ---------------- shared mma helpers ----------------
__device__ __forceinline__ void ldm_x4(uint32_t* r, uint32_t addr) {
    asm volatile("ldmatrix.sync.aligned.m8n8.x4.shared.b16 {%0,%1,%2,%3}, [%4];"
                 : "=r"(r[0]), "=r"(r[1]), "=r"(r[2]), "=r"(r[3]) : "r"(addr));
}
__device__ __forceinline__ void mma_fp16(float* c, const uint32_t* a, const uint32_t* b) {
    asm volatile("mma.sync.aligned.m16n8k16.row.col.f32.f16.f16.f32 "
                 "{%0,%1,%2,%3}, {%4,%5,%6,%7}, {%8,%9}, {%0,%1,%2,%3};"
                 : "+f"(c[0]), "+f"(c[1]), "+f"(c[2]), "+f"(c[3])
                 : "r"(a[0]), "r"(a[1]), "r"(a[2]), "r"(a[3]), "r"(b[0]), "r"(b[1]));
}
__device__ __forceinline__ uint32_t smem_u32(const void* p) {
    uint32_t a;
    asm("{ .reg .u64 t; cvta.to.shared.u64 t, %1; cvt.u32.u64 %0, t; }" : "=r"(a) : "l"(p));
    return a;
}
__device__ __forceinline__ void cp16(uint32_t dst, const void* src) {
    asm volatile("cp.async.cg.shared.global [%0], [%1], 16;" :: "r"(dst), "l"(src));
}
#define CP_COMMIT() asm volatile("cp.async.commit_group;" ::: "memory")
#define CP_WAIT1()  asm volatile("cp.async.wait_group 1;" ::: "memory")
#define CP_WAIT0()  asm volatile("cp.async.wait_group 0;" ::: "memory")

// ---------------------------------------------------------------------------
// GEMM1: Sup = G[k] @ Comb, fp16 2-pass (A split hi/lo, B truncated).
// 3-stage cp.async pipeline, k-chunk 32, ONE syncthreads per iteration
// (wait -> sync -> prefetch -> compute; prefetch after sync = no WAR hazard).
// CTA tile 128x96, grid (22,4,3), 256 threads. Row stride 80 B.
// ---------------------------------------------------------------------------
#define ROWB 80
#define S1_AHI 0
#define S1_ALO 10240
#define S1_B   20480          // 96*80 = 7680
#define STG1   28160
#define SMEM_G1 (3*STG1)      // 84480 >= 128*97*4 = 49664 epilogue buffer

__global__ __launch_bounds__(256) void gemm1_mma_kernel() {
    extern __shared__ char smg[];
    const int kk = blockIdx.z;
    const int bm = blockIdx.y;
    const int bn = blockIdx.x;
    const int tid  = threadIdx.x;
    const int wid  = tid >> 5;
    const int lane = tid & 31;
    const int wm = wid & 3;
    const int wn = wid >> 2;
    const uint32_t sm0 = smem_u32(smg);

    const __half* Ahi0 = g_gHi + kk*Nq*Nq + bm*128*Nq;
    const __half* Alo0 = g_gLo + kk*Nq*Nq + bm*128*Nq;
    const __half* B0   = g_ct + bn*96*Nq;

    // staging: A 512 cps/array (2/thread); B 384 cps (1/thread + tid<128)
    const int rA0 = tid >> 2,          qA0 = (tid & 3);
    const int rA1 = (tid + 256) >> 2,  qA1 = (tid & 3);

    float acc[2][6][4];
    #pragma unroll
    for (int i = 0; i < 2; i++)
        #pragma unroll
        for (int j = 0; j < 6; j++)
            #pragma unroll
            for (int r = 0; r < 4; r++) acc[i][j][r] = 0.0f;

    const uint32_t aOff = (uint32_t)((lane & 15) * ROWB + (lane >> 4) * 16);
    const uint32_t bOff = (uint32_t)(((lane & 7) + ((lane >> 4) << 3)) * ROWB
                                     + (((lane >> 3) & 1) * 16));

    // prefetch chunks 0, 1
    #pragma unroll
    for (int pc = 0; pc < 2; pc++) {
        const uint32_t base = sm0 + pc*STG1;
        const int kt = pc * 32;
        cp16(base + S1_AHI + rA0*ROWB + qA0*16, Ahi0 + rA0*Nq + kt + qA0*8);
        cp16(base + S1_ALO + rA0*ROWB + qA0*16, Alo0 + rA0*Nq + kt + qA0*8);
        cp16(base + S1_AHI + rA1*ROWB + qA1*16, Ahi0 + rA1*Nq + kt + qA1*8);
        cp16(base + S1_ALO + rA1*ROWB + qA1*16, Alo0 + rA1*Nq + kt + qA1*8);
        cp16(base + S1_B   + rA0*ROWB + qA0*16, B0 + rA0*Nq + kt + qA0*8);
        if (tid < 128)
            cp16(base + S1_B + rA1*ROWB + qA1*16, B0 + rA1*Nq + kt + qA1*8);
        CP_COMMIT();
    }

    for (int c = 0; c < 16; c++) {
        if (c < 15) { CP_WAIT1(); } else { CP_WAIT0(); }
        __syncthreads();    // all warps: chunk c resident; done computing c-1

        if (c < 14) {       // prefetch c+2 (stage last read at iter c-1: safe)
            const uint32_t base = sm0 + ((c + 2) % 3)*STG1;
            const int kt = (c + 2) * 32;
            cp16(base + S1_AHI + rA0*ROWB + qA0*16, Ahi0 + rA0*Nq + kt + qA0*8);
            cp16(base + S1_ALO + rA0*ROWB + qA0*16, Alo0 + rA0*Nq + kt + qA0*8);
            cp16(base + S1_AHI + rA1*ROWB + qA1*16, Ahi0 + rA1*Nq + kt + qA1*8);
            cp16(base + S1_ALO + rA1*ROWB + qA1*16, Alo0 + rA1*Nq + kt + qA1*8);
            cp16(base + S1_B   + rA0*ROWB + qA0*16, B0 + rA0*Nq + kt + qA0*8);
            if (tid < 128)
                cp16(base + S1_B + rA1*ROWB + qA1*16, B0 + rA1*Nq + kt + qA1*8);
            CP_COMMIT();
        }

        const uint32_t base = sm0 + (c % 3)*STG1;
        #pragma unroll
        for (int ks = 0; ks < 2; ks++) {
            const uint32_t kByte = (uint32_t)(ks * 32);
            uint32_t fAhi[2][4], fAlo[2][4], fB[3][4];

            #pragma unroll
            for (int mf = 0; mf < 2; mf++)
                ldm_x4(fAhi[mf], base + S1_AHI + (wm*32 + mf*16)*ROWB + aOff + kByte);
            #pragma unroll
            for (int q = 0; q < 3; q++)
                ldm_x4(fB[q], base + S1_B + (wn*48 + q*16)*ROWB + bOff + kByte);
            #pragma unroll
            for (int mf = 0; mf < 2; mf++)
                #pragma unroll
                for (int q = 0; q < 3; q++) {
                    mma_fp16(acc[mf][2*q+0], fAhi[mf], &fB[q][0]);
                    mma_fp16(acc[mf][2*q+1], fAhi[mf], &fB[q][2]);
                }

            #pragma unroll
            for (int mf = 0; mf < 2; mf++)
                ldm_x4(fAlo[mf], base + S1_ALO + (wm*32 + mf*16)*ROWB + aOff + kByte);
            #pragma unroll
            for (int mf = 0; mf < 2; mf++)
                #pragma unroll
                for (int q = 0; q < 3; q++) {
                    mma_fp16(acc[mf][2*q+0], fAlo[mf], &fB[q][0]);
                    mma_fp16(acc[mf][2*q+1], fAlo[mf], &fB[q][2]);
                }
        }
    }
    __syncthreads();   // pipeline buffers dead; reuse smem for epilogue

    // Epilogue: stage fp32 tile (stride 97), coalesced split-store
    float* fs = (float*)smg;
    const int quad = lane >> 2;
    const int tq   = lane & 3;
    #pragma unroll
    for (int mf = 0; mf < 2; mf++)
        #pragma unroll
        for (int nf = 0; nf < 6; nf++)
            #pragma unroll
            for (int r = 0; r < 4; r++) {
                int m = wm*32 + mf*16 + ((r >> 1) << 3) + quad;
                int c = wn*48 + nf*8 + tq*2 + (r & 1);
                fs[m*97 + c] = acc[mf][nf][r];
            }
    __syncthreads();
    for (int idx = tid; idx < 128*96; idx += 256) {
        int row = idx / 96;
        int c   = idx - row*96;
        float v = fs[row*97 + c];
        int col = bn*96 + c;
        int b = col / Pq;
        int p = col - b*Pq;
        __half hi, lo; split_fp16(v, hi, lo);
        int o = (b*Nq + bm*128 + row)*KS2 + kk*Pq + p;
        g_supHi[o] = hi;
        g_supLo[o] = lo;
    }
}

// ---------------------------------------------------------------------------
// GEMM2 via mma.sync, fp16 2-pass (sup split, W truncated), double-buffered.
// Update variant also prefills next step's x columns of combT (set_x fused).
// ---------------------------------------------------------------------------
#define RB2 48

template<int OUT, bool GATE>
__global__ __launch_bounds__(256) void gemm2m_kernel(const float* __restrict__ bias,
                                                     float* __restrict__ out,
                                                     const float* __restrict__ x_seq,
                                                     int t, int is_last) {
    constexpr int NWN = OUT/64;
    constexpr int NWM = 8/NWN;
    constexpr int MT  = 128/NWM;
    constexpr int MF  = MT/16;
    constexpr int OFF2_ALO = 128*RB2;
    constexpr int OFF2_W   = 2*128*RB2;
    constexpr int STG2     = 2*128*RB2 + OUT*RB2;
    constexpr int SW       = OUT + 1;

    extern __shared__ char smg[];

    const int bm = blockIdx.x;
    const int tid  = threadIdx.x;
    const int wid  = tid >> 5;
    const int lane = tid & 31;
    const int wm = wid % NWM;
    const int wn = wid / NWM;
    const uint32_t sm0 = smem_u32(smg);

    const __half* Wt   = GATE ? g_Wtg : g_Wtu;
    const __half* AHi0 = g_supHi + (size_t)bm*128*KS2;
    const __half* ALo0 = g_supLo + (size_t)bm*128*KS2;

    const int rA = tid >> 1, hA = tid & 1;

    float acc[MF][8][4];
    #pragma unroll
    for (int mf = 0; mf < MF; mf++)
        #pragma unroll
        for (int nf = 0; nf < 8; nf++)
            #pragma unroll
            for (int r = 0; r < 4; r++)
                acc[mf][nf][r] = bias[wn*64 + nf*8 + (lane & 3)*2 + (r & 1)];

    const uint32_t aOff = (uint32_t)((lane & 15) * RB2 + (lane >> 4) * 16);
    const uint32_t bOff = (uint32_t)(((lane & 7) + ((lane >> 4) << 3)) * RB2
                                     + (((lane >> 3) & 1) * 16));

    {   // prefetch chunk 0
        const uint32_t base = sm0;
        cp16(base + 0        + rA*RB2 + hA*16, AHi0 + rA*KS2 + hA*8);
        cp16(base + OFF2_ALO + rA*RB2 + hA*16, ALo0 + rA*KS2 + hA*8);
        if (OUT == 128) {
            cp16(base + OFF2_W + rA*RB2 + hA*16, Wt + rA*KS2 + hA*8);
        } else if (tid < 128) {
            cp16(base + OFF2_W + rA*RB2 + hA*16, Wt + rA*KS2 + hA*8);
        }
        CP_COMMIT();
    }

    for (int c = 0; c < 13; c++) {
        if (c < 12) {
            const uint32_t base = sm0 + ((c + 1) & 1) * STG2;
            const int kt = (c + 1) * 16;
            cp16(base + 0        + rA*RB2 + hA*16, AHi0 + rA*KS2 + kt + hA*8);
            cp16(base + OFF2_ALO + rA*RB2 + hA*16, ALo0 + rA*KS2 + kt + hA*8);
            if (OUT == 128) {
                cp16(base + OFF2_W + rA*RB2 + hA*16, Wt + rA*KS2 + kt + hA*8);
            } else if (tid < 128) {
                cp16(base + OFF2_W + rA*RB2 + hA*16, Wt + rA*KS2 + kt + hA*8);
            }
            CP_COMMIT();
            CP_WAIT1();
        } else {
            CP_WAIT0();
        }
        __syncthreads();

        const uint32_t base = sm0 + (c & 1) * STG2;
        uint32_t fAhi[MF][4], fAlo[MF][4], fW[4][4];

        #pragma unroll
        for (int mf = 0; mf < MF; mf++)
            ldm_x4(fAhi[mf], base + 0 + (wm*MT + mf*16)*RB2 + aOff);
        #pragma unroll
        for (int q = 0; q < 4; q++)
            ldm_x4(fW[q], base + OFF2_W + (wn*64 + q*16)*RB2 + bOff);
        #pragma unroll
        for (int mf = 0; mf < MF; mf++)
            #pragma unroll
            for (int q = 0; q < 4; q++) {
                mma_fp16(acc[mf][2*q+0], fAhi[mf], &fW[q][0]);
                mma_fp16(acc[mf][2*q+1], fAhi[mf], &fW[q][2]);
            }

        #pragma unroll
        for (int mf = 0; mf < MF; mf++)
            ldm_x4(fAlo[mf], base + OFF2_ALO + (wm*MT + mf*16)*RB2 + aOff);
        #pragma unroll
        for (int mf = 0; mf < MF; mf++)
            #pragma unroll
            for (int q = 0; q < 4; q++) {
                mma_fp16(acc[mf][2*q+0], fAlo[mf], &fW[q][0]);
                mma_fp16(acc[mf][2*q+1], fAlo[mf], &fW[q][2]);
            }
        __syncthreads();
    }

    // ---- Epilogue: stage acc in smem fp32 [128][SW], then coalesced passes.
    float* fs = (float*)smg;
    const int quad = lane >> 2;
    const int tq   = lane & 3;
    #pragma unroll
    for (int mf = 0; mf < MF; mf++)
        #pragma unroll
        for (int nf = 0; nf < 8; nf++)
            #pragma unroll
            for (int r = 0; r < 4; r++) {
                int rl = wm*MT + mf*16 + ((r >> 1) << 3) + quad;
                int o  = wn*64 + nf*8 + tq*2 + (r & 1);
                fs[rl*SW + o] = acc[mf][nf][r];
            }
    __syncthreads();

    if (GATE) {
        for (int idx = tid; idx < 128*OUT; idx += 256) {
            int rl = idx >> 7;
            int o  = idx & 127;
            int row = bm*128 + rl;
            float zv = 1.0f / (1.0f + __expf(-fs[rl*SW + o]));
            if (o < Hq) {
                g_z[row*Hq + o] = zv;
            } else {
                fs[rl*SW + o] = zv * g_h[row*Hq + (o - Hq)];
            }
        }
        __syncthreads();
        for (int idx = tid; idx < Hq*128; idx += 256) {
            int hid = idx >> 7;
            int rl  = idx & 127;
            int row = bm*128 + rl;
            int b = row >> 9;
            int n = row & (Nq - 1);
            g_ct[(b*Pq + Cq + hid)*Nq + n] = __float2half(fs[rl*SW + Hq + hid]);
        }
    } else {
        for (int idx = tid; idx < 128*OUT; idx += 256) {
            int rl = idx >> 6;
            int o  = idx & 63;
            int row = bm*128 + rl;
            float hc   = tanhf(fs[rl*SW + o]);
            float zv   = g_z[row*Hq + o];
            float hold = g_h[row*Hq + o];
            float hnew = (1.0f - zv)*hold + zv*hc;
            g_h[row*Hq + o] = hnew;
            if (is_last) out[row*Hq + o] = hnew;
            fs[rl*SW + o] = hnew;
        }
        __syncthreads();
        for (int idx = tid; idx < Hq*128; idx += 256) {
            int o  = idx >> 7;
            int rl = idx & 127;
            int row = bm*128 + rl;
            int b = row >> 9;
            int n = row & (Nq - 1);
            g_ct[(b*Pq + Cq + o)*Nq + n] = __float2half(fs[rl*SW + o]);
        }
        // fused set_x for step t+1 (256 elems: p in {0,1} x 128 rows)
        if (!is_last) {
            int p  = tid >> 7;
            int rl = tid & 127;
            int row = bm*128 + rl;
            int b = row >> 9;
            int n = row & (Nq - 1);
            g_ct[(b*Pq + p)*Nq + n] =
                __float2half(x_seq[((b*Tq + (t + 1))*Nq + n)*Cq + p]);
        }
    }
}

// Host-side dynamic smem sizes for gemm2m (max of pipeline, epilogue buffer)
#define STG2_GATE (2*128*RB2 + OUTG*RB2)            // 18432
#define STG2_UPD  (2*128*RB2 + Hq*RB2)              // 15360
#define SM2_GATE  ((2*STG2_GATE) > (128*(OUTG+1)*4) ? (2*STG2_GATE) : (128*(OUTG+1)*4))
#define SM2_UPD   ((2*STG2_UPD)  > (128*(Hq+1)*4)  ? (2*STG2_UPD)  : (128*(Hq+1)*4))

// ---------------------------------------------------------------------------
// kernel_launch
// Inputs: G, x_seq, init_h, W_gate, b_gate, W_update, b_update
// ---------------------------------------------------------------------------
extern "C" void kernel_launch(void* const* d_in, const int* in_sizes, int n_in,
                              void* d_out, int out_size) {
    const float* G        = (const float*)d_in[0];
    const float* x_seq    = (const float*)d_in[1];
    const float* init_h   = (const float*)d_in[2];
    const float* W_gate   = (const float*)d_in[3];
    const float* b_gate   = (const float*)d_in[4];
    const float* W_update = (const float*)d_in[5];
    const float* b_update = (const float*)d_in[6];
    float* out = (float*)d_out;

    cudaFuncSetAttribute(gemm1_mma_kernel,
                         cudaFuncAttributeMaxDynamicSharedMemorySize, SMEM_G1);
    cudaFuncSetAttribute(gemm2m_kernel<OUTG, true>,
                         cudaFuncAttributeMaxDynamicSharedMemorySize, SM2_GATE);
    cudaFuncSetAttribute(gemm2m_kernel<Hq, false>,
                         cudaFuncAttributeMaxDynamicSharedMemorySize, SM2_UPD);

    prep_g_kernel<<<(Kq*Nq*Nq + 255)/256, 256>>>(G);
    prep_w_kernel<<<((OUTG + Hq)*KS2 + 255)/256, 256>>>(W_gate, W_update);
    init_kernel<<<(Bq*Nq*Hq + 255)/256, 256>>>(init_h);
    set_x_kernel<<<(Bq*Nq*Cq + 255)/256, 256>>>(x_seq, 0);   // t = 0 only

    dim3 g1(NCOLS/96, Nq/128, Kq);   // (22, 4, 3)
    for (int t = 0; t < Tq; t++) {
        gemm1_mma_kernel<<<g1, 256, SMEM_G1>>>();
        gemm2m_kernel<OUTG, true><<<NROWS/128, 256, SM2_GATE>>>(b_gate, out, x_seq, t, 0);
        gemm1_mma_kernel<<<g1, 256, SMEM_G1>>>();
        gemm2m_kernel<Hq, false><<<NROWS/128, 256, SM2_UPD>>>(b_update, out, x_seq, t, t == Tq - 1);
    }
}

// round 15
// speedup vs baseline: 1.4966x; 1.1998x over previous
#include <cuda_runtime.h>
#include <cuda_fp16.h>
#include <cstdint>
#include <math.h>

// Problem constants
#define Bq 32
#define Tq 12
#define Nq 512
#define Cq 2
#define Hq 64
#define Kq 3
#define Pq 66            // C + H
#define NCOLS (Bq*Pq)    // 2112
#define KP  (Kq*Pq)      // 198
#define KS2 208          // sup row stride in fp16
#define OUTG (2*Hq)      // 128
#define NROWS (Bq*Nq)    // 16384
#define NCTA 132
#define NTHR 512

// ---------------- device state ----------------
__device__ float g_h[Bq*Nq*Hq];
__device__ float g_z[Bq*Nq*Hq];
__device__ __half g_gHi[Kq*Nq*Nq];
__device__ __half g_gLo[Kq*Nq*Nq];
__device__ __half g_ct[NCOLS*Nq];
__device__ __half g_supHi[NROWS*KS2];
__device__ __half g_supLo[NROWS*KS2];
__device__ __half g_Wtg[OUTG*KS2];
__device__ __half g_Wtu[Hq*KS2];
__device__ unsigned g_bcnt;
__device__ unsigned g_bflag;

__device__ __forceinline__ void split_fp16(float v, __half& hi, __half& lo) {
    hi = __float2half(v);
    lo = __float2half(v - __half2float(hi));
}

// ---------------- helpers ----------------
__device__ __forceinline__ void ldm_x4(uint32_t* r, uint32_t addr) {
    asm volatile("ldmatrix.sync.aligned.m8n8.x4.shared.b16 {%0,%1,%2,%3}, [%4];"
                 : "=r"(r[0]), "=r"(r[1]), "=r"(r[2]), "=r"(r[3]) : "r"(addr));
}
__device__ __forceinline__ void mma_fp16(float* c, const uint32_t* a, const uint32_t* b) {
    asm volatile("mma.sync.aligned.m16n8k16.row.col.f32.f16.f16.f32 "
                 "{%0,%1,%2,%3}, {%4,%5,%6,%7}, {%8,%9}, {%0,%1,%2,%3};"
                 : "+f"(c[0]), "+f"(c[1]), "+f"(c[2]), "+f"(c[3])
                 : "r"(a[0]), "r"(a[1]), "r"(a[2]), "r"(a[3]), "r"(b[0]), "r"(b[1]));
}
__device__ __forceinline__ uint32_t smem_u32(const void* p) {
    uint32_t a;
    asm("{ .reg .u64 t; cvta.to.shared.u64 t, %1; cvt.u32.u64 %0, t; }" : "=r"(a) : "l"(p));
    return a;
}
__device__ __forceinline__ void cp16(uint32_t dst, const void* src) {
    asm volatile("cp.async.cg.shared.global [%0], [%1], 16;" :: "r"(dst), "l"(src));
}
#define CP_COMMIT() asm volatile("cp.async.commit_group;" ::: "memory")
#define CP_WAIT1()  asm volatile("cp.async.wait_group 1;" ::: "memory")
#define CP_WAIT0()  asm volatile("cp.async.wait_group 0;" ::: "memory")

// Sense-reversal grid barrier. Safe: all NCTA CTAs resident (132 <= 148 SMs),
// every CTA participates in every barrier. A late-starting CTA cannot observe
// a flipped flag before its own arrival (flip requires all NCTA arrivals).
__device__ __forceinline__ void grid_sync(unsigned &sense) {
    __syncthreads();
    if (threadIdx.x == 0) {
        unsigned target = sense ^ 1u;
        __threadfence();
        unsigned old = atomicAdd(&g_bcnt, 1u);
        if (old == NCTA - 1) {
            atomicExch(&g_bcnt, 0u);
            __threadfence();
            *((volatile unsigned*)&g_bflag) = target;
        } else {
            while (*((volatile unsigned*)&g_bflag) != target) __nanosleep(64);
        }
        __threadfence();
    }
    __syncthreads();
    sense ^= 1u;
}

// ---------------------------------------------------------------------------
// GEMM1 phase: Sup = G[k] @ Comb, fp16 2-pass (A split hi/lo, B truncated).
// CTA tile 128x192, 512 threads (16 warps = 4M x 4N, warp tile 32x48).
// 3-stage cp.async pipeline, k-chunk 32, one syncthreads per chunk.
// Job map: cta -> (kk, bm, bn) with 132 = 3*4*11 jobs.
// ---------------------------------------------------------------------------
#define ROWB 80
#define S1_AHI 0
#define S1_ALO 10240
#define S1_B   20480          // 192*80 = 15360
#define STG1   35840
#define SMEM_PK (3*STG1)      // 107520; >= epilogue 128*193*4 = 98816

__device__ __noinline__ void gemm1_phase(char* smg, int cta, int tid) {
    const int kk  = cta / 44;
    const int rem = cta - kk*44;
    const int bm  = rem / 11;
    const int bn  = rem - bm*11;
    const int wid  = tid >> 5;
    const int lane = tid & 31;
    const int wm = wid & 3;
    const int wn = wid >> 2;            // 0..3
    const uint32_t sm0 = smem_u32(smg);

    const __half* Ahi0 = g_gHi + kk*Nq*Nq + bm*128*Nq;
    const __half* Alo0 = g_gLo + kk*Nq*Nq + bm*128*Nq;
    const __half* B0   = g_ct + bn*192*Nq;

    const int rS = tid >> 2, qS = tid & 3;        // A rows 0..127
    const int rB2 = (tid + 512) >> 2;             // B rows 128..191 (tid<256)

    float acc[2][6][4];
    #pragma unroll
    for (int i = 0; i < 2; i++)
        #pragma unroll
        for (int j = 0; j < 6; j++)
            #pragma unroll
            for (int r = 0; r < 4; r++) acc[i][j][r] = 0.0f;

    const uint32_t aOff = (uint32_t)((lane & 15) * ROWB + (lane >> 4) * 16);
    const uint32_t bOff = (uint32_t)(((lane & 7) + ((lane >> 4) << 3)) * ROWB
                                     + (((lane >> 3) & 1) * 16));

    // prefetch chunks 0, 1
    #pragma unroll
    for (int pc = 0; pc < 2; pc++) {
        const uint32_t base = sm0 + pc*STG1;
        const int kt = pc * 32;
        cp16(base + S1_AHI + rS*ROWB + qS*16, Ahi0 + rS*Nq + kt + qS*8);
        cp16(base + S1_ALO + rS*ROWB + qS*16, Alo0 + rS*Nq + kt + qS*8);
        cp16(base + S1_B   + rS*ROWB + qS*16, B0 + rS*Nq + kt + qS*8);
        if (tid < 256)
            cp16(base + S1_B + rB2*ROWB + qS*16, B0 + rB2*Nq + kt + qS*8);
        CP_COMMIT();
    }

    for (int c = 0; c < 16; c++) {
        if (c < 15) { CP_WAIT1(); } else { CP_WAIT0(); }
        __syncthreads();

        if (c < 14) {
            const uint32_t base = sm0 + ((c + 2) % 3)*STG1;
            const int kt = (c + 2) * 32;
            cp16(base + S1_AHI + rS*ROWB + qS*16, Ahi0 + rS*Nq + kt + qS*8);
            cp16(base + S1_ALO + rS*ROWB + qS*16, Alo0 + rS*Nq + kt + qS*8);
            cp16(base + S1_B   + rS*ROWB + qS*16, B0 + rS*Nq + kt + qS*8);
            if (tid < 256)
                cp16(base + S1_B + rB2*ROWB + qS*16, B0 + rB2*Nq + kt + qS*8);
            CP_COMMIT();
        }

        const uint32_t base = sm0 + (c % 3)*STG1;
        #pragma unroll
        for (int ks = 0; ks < 2; ks++) {
            const uint32_t kByte = (uint32_t)(ks * 32);
            uint32_t fAhi[2][4], fAlo[2][4], fB[3][4];

            #pragma unroll
            for (int mf = 0; mf < 2; mf++)
                ldm_x4(fAhi[mf], base + S1_AHI + (wm*32 + mf*16)*ROWB + aOff + kByte);
            #pragma unroll
            for (int q = 0; q < 3; q++)
                ldm_x4(fB[q], base + S1_B + (wn*48 + q*16)*ROWB + bOff + kByte);
            #pragma unroll
            for (int mf = 0; mf < 2; mf++)
                #pragma unroll
                for (int q = 0; q < 3; q++) {
                    mma_fp16(acc[mf][2*q+0], fAhi[mf], &fB[q][0]);
                    mma_fp16(acc[mf][2*q+1], fAhi[mf], &fB[q][2]);
                }

            #pragma unroll
            for (int mf = 0; mf < 2; mf++)
                ldm_x4(fAlo[mf], base + S1_ALO + (wm*32 + mf*16)*ROWB + aOff + kByte);
            #pragma unroll
            for (int mf = 0; mf < 2; mf++)
                #pragma unroll
                for (int q = 0; q < 3; q++) {
                    mma_fp16(acc[mf][2*q+0], fAlo[mf], &fB[q][0]);
                    mma_fp16(acc[mf][2*q+1], fAlo[mf], &fB[q][2]);
                }
        }
    }
    __syncthreads();   // pipeline buffers dead; reuse smem for epilogue

    float* fs = (float*)smg;   // 128 x 192, stride 193
    const int quad = lane >> 2;
    const int tq   = lane & 3;
    #pragma unroll
    for (int mf = 0; mf < 2; mf++)
        #pragma unroll
        for (int nf = 0; nf < 6; nf++)
            #pragma unroll
            for (int r = 0; r < 4; r++) {
                int m = wm*32 + mf*16 + ((r >> 1) << 3) + quad;
                int c = wn*48 + nf*8 + tq*2 + (r & 1);
                fs[m*193 + c] = acc[mf][nf][r];
            }
    __syncthreads();
    for (int idx = tid; idx < 128*192; idx += NTHR) {
        int row = idx / 192;
        int c   = idx - row*192;
        float v = fs[row*193 + c];
        int col = bn*192 + c;
        int b = col / Pq;
        int p = col - b*Pq;
        __half hi, lo; split_fp16(v, hi, lo);
        int o = (b*Nq + bm*128 + row)*KS2 + kk*Pq + p;
        g_supHi[o] = hi;
        g_supLo[o] = lo;
    }
}

// ---------------------------------------------------------------------------
// GEMM2 phase: sup @ W, fp16 2-pass, 512 threads (16 warps = 8M x 2N).
// Warp tile 16 x (OUT/2). Only CTAs < 128 call this.
// ---------------------------------------------------------------------------
#define RB2 48

template<int OUT, bool GATE>
__device__ __noinline__ void gemm2_phase(char* smg, int cta, int tid,
                                         const float* __restrict__ bias,
                                         float* __restrict__ out,
                                         const float* __restrict__ x_seq,
                                         int t, int is_last) {
    constexpr int NT  = OUT/2;         // 64 or 32
    constexpr int QF  = NT/16;         // 4 or 2
    constexpr int NF8 = NT/8;          // 8 or 4
    constexpr int OFF2_ALO = 128*RB2;            // 6144
    constexpr int OFF2_W   = 2*128*RB2;          // 12288
    constexpr int STG2     = 2*128*RB2 + OUT*RB2;
    constexpr int SW       = OUT + 1;

    const int bm = cta;
    const int wid  = tid >> 5;
    const int lane = tid & 31;
    const int wm = wid & 7;            // rows wm*16
    const int wn = wid >> 3;           // cols wn*NT
    const uint32_t sm0 = smem_u32(smg);

    const __half* Wt   = GATE ? g_Wtg : g_Wtu;
    const __half* AHi0 = g_supHi + (size_t)bm*128*KS2;
    const __half* ALo0 = g_supLo + (size_t)bm*128*KS2;

    const int rA = (tid & 255) >> 1, hA = tid & 1;

    float acc[NF8][4];
    #pragma unroll
    for (int nf = 0; nf < NF8; nf++)
        #pragma unroll
        for (int r = 0; r < 4; r++)
            acc[nf][r] = bias[wn*NT + nf*8 + (lane & 3)*2 + (r & 1)];

    const uint32_t aOff = (uint32_t)((lane & 15) * RB2 + (lane >> 4) * 16);
    const uint32_t bOff = (uint32_t)(((lane & 7) + ((lane >> 4) << 3)) * RB2
                                     + (((lane >> 3) & 1) * 16));

    {   // prefetch chunk 0
        const uint32_t base = sm0;
        if (tid < 256) cp16(base + 0        + rA*RB2 + hA*16, AHi0 + rA*KS2 + hA*8);
        else           cp16(base + OFF2_ALO + rA*RB2 + hA*16, ALo0 + rA*KS2 + hA*8);
        if (tid < OUT*2) {
            int rw = tid >> 1, hw = tid & 1;
            cp16(base + OFF2_W + rw*RB2 + hw*16, Wt + rw*KS2 + hw*8);
        }
        CP_COMMIT();
    }

    for (int c = 0; c < 13; c++) {
        if (c < 12) {
            const uint32_t base = sm0 + ((c + 1) & 1) * STG2;
            const int kt = (c + 1) * 16;
            if (tid < 256) cp16(base + 0        + rA*RB2 + hA*16, AHi0 + rA*KS2 + kt + hA*8);
            else           cp16(base + OFF2_ALO + rA*RB2 + hA*16, ALo0 + rA*KS2 + kt + hA*8);
            if (tid < OUT*2) {
                int rw = tid >> 1, hw = tid & 1;
                cp16(base + OFF2_W + rw*RB2 + hw*16, Wt + rw*KS2 + kt + hw*8);
            }
            CP_COMMIT();
            CP_WAIT1();
        } else {
            CP_WAIT0();
        }
        __syncthreads();

        const uint32_t base = sm0 + (c & 1) * STG2;
        uint32_t fA[4], fW[QF][4];

        ldm_x4(fA, base + 0 + (wm*16)*RB2 + aOff);
        #pragma unroll
        for (int q = 0; q < QF; q++)
            ldm_x4(fW[q], base + OFF2_W + (wn*NT + q*16)*RB2 + bOff);
        #pragma unroll
        for (int q = 0; q < QF; q++) {
            mma_fp16(acc[2*q+0], fA, &fW[q][0]);
            mma_fp16(acc[2*q+1], fA, &fW[q][2]);
        }

        ldm_x4(fA, base + OFF2_ALO + (wm*16)*RB2 + aOff);
        #pragma unroll
        for (int q = 0; q < QF; q++) {
            mma_fp16(acc[2*q+0], fA, &fW[q][0]);
            mma_fp16(acc[2*q+1], fA, &fW[q][2]);
        }
        __syncthreads();
    }

    // Epilogue: stage fp32 [128][SW], coalesced passes
    float* fs = (float*)smg;
    const int quad = lane >> 2;
    const int tq   = lane & 3;
    #pragma unroll
    for (int nf = 0; nf < NF8; nf++)
        #pragma unroll
        for (int r = 0; r < 4; r++) {
            int rl = wm*16 + ((r >> 1) << 3) + quad;
            int o  = wn*NT + nf*8 + tq*2 + (r & 1);
            fs[rl*SW + o] = acc[nf][r];
        }
    __syncthreads();

    if (GATE) {
        for (int idx = tid; idx < 128*OUT; idx += NTHR) {
            int rl = idx >> 7;          // OUT = 128
            int o  = idx & 127;
            int row = bm*128 + rl;
            float zv = 1.0f / (1.0f + __expf(-fs[rl*SW + o]));
            if (o < Hq) {
                g_z[row*Hq + o] = zv;
            } else {
                fs[rl*SW + o] = zv * g_h[row*Hq + (o - Hq)];
            }
        }
        __syncthreads();
        for (int idx = tid; idx < Hq*128; idx += NTHR) {
            int hid = idx >> 7;
            int rl  = idx & 127;
            int row = bm*128 + rl;
            int b = row >> 9;
            int n = row & (Nq - 1);
            g_ct[(b*Pq + Cq + hid)*Nq + n] = __float2half(fs[rl*SW + Hq + hid]);
        }
    } else {
        for (int idx = tid; idx < 128*OUT; idx += NTHR) {
            int rl = idx >> 6;          // OUT = 64
            int o  = idx & 63;
            int row = bm*128 + rl;
            float hc   = tanhf(fs[rl*SW + o]);
            float zv   = g_z[row*Hq + o];
            float hold = g_h[row*Hq + o];
            float hnew = (1.0f - zv)*hold + zv*hc;
            g_h[row*Hq + o] = hnew;
            if (is_last) out[row*Hq + o] = hnew;
            fs[rl*SW + o] = hnew;
        }
        __syncthreads();
        for (int idx = tid; idx < Hq*128; idx += NTHR) {
            int o  = idx >> 7;
            int rl = idx & 127;
            int row = bm*128 + rl;
            int b = row >> 9;
            int n = row & (Nq - 1);
            g_ct[(b*Pq + Cq + o)*Nq + n] = __float2half(fs[rl*SW + o]);
        }
        if (!is_last && tid < 256) {   // fused set_x for t+1
            int p  = tid >> 7;
            int rl = tid & 127;
            int row = bm*128 + rl;
            int b = row >> 9;
            int n = row & (Nq - 1);
            g_ct[(b*Pq + p)*Nq + n] =
                __float2half(x_seq[((b*Tq + (t + 1))*Nq + n)*Cq + p]);
        }
    }
}

// ---------------------------------------------------------------------------
// Persistent kernel: init + 12 steps x 4 phases, grid-synced.
// ---------------------------------------------------------------------------
__global__ void __launch_bounds__(NTHR, 1) encoder_persistent(
    const float* __restrict__ G, const float* __restrict__ x_seq,
    const float* __restrict__ init_h,
    const float* __restrict__ Wg, const float* __restrict__ bg,
    const float* __restrict__ Wu, const float* __restrict__ bu,
    float* __restrict__ out) {
    extern __shared__ char smg[];
    const int cta = blockIdx.x;
    const int tid = threadIdx.x;
    unsigned sense = *((volatile unsigned*)&g_bflag);

    // ---- init phase ----
    const int gs = cta*NTHR + tid;
    const int gstr = NCTA*NTHR;
    for (int idx = gs; idx < Kq*Nq*Nq; idx += gstr) {
        __half hi, lo; split_fp16(G[idx], hi, lo);
        g_gHi[idx] = hi; g_gLo[idx] = lo;
    }
    for (int idx = gs; idx < (OUTG + Hq)*KS2; idx += gstr) {
        if (idx < OUTG*KS2) {
            int o = idx / KS2, k = idx % KS2;
            g_Wtg[idx] = __float2half((k < KP) ? Wg[k*OUTG + o] : 0.0f);
        } else {
            int q = idx - OUTG*KS2;
            int o = q / KS2, k = q % KS2;
            g_Wtu[q] = __float2half((k < KP) ? Wu[k*Hq + o] : 0.0f);
        }
    }
    for (int idx = gs; idx < Bq*Nq*Hq; idx += gstr) {
        float v = init_h[idx];
        g_h[idx] = v;
        int hid = idx % Hq;
        int row = idx / Hq;
        int b = row / Nq;
        int n = row % Nq;
        g_ct[(b*Pq + Cq + hid)*Nq + n] = __float2half(v);
    }
    for (int idx = gs; idx < Bq*Nq*Cq; idx += gstr) {
        int p = idx % Cq;
        int rest = idx / Cq;
        int n = rest % Nq;
        int b = rest / Nq;
        g_ct[(b*Pq + p)*Nq + n] = __float2half(x_seq[((b*Tq + 0)*Nq + n)*Cq + p]);
    }
    grid_sync(sense);

    for (int t = 0; t < Tq; t++) {
        gemm1_phase(smg, cta, tid);
        grid_sync(sense);
        if (cta < 128) gemm2_phase<OUTG, true>(smg, cta, tid, bg, out, x_seq, t, 0);
        grid_sync(sense);
        gemm1_phase(smg, cta, tid);
        grid_sync(sense);
        if (cta < 128) gemm2_phase<Hq, false>(smg, cta, tid, bu, out, x_seq, t, t == Tq - 1);
        grid_sync(sense);
    }
}

// ---------------------------------------------------------------------------
// kernel_launch
// Inputs: G, x_seq, init_h, W_gate, b_gate, W_update, b_update
// ---------------------------------------------------------------------------
extern "C" void kernel_launch(void* const* d_in, const int* in_sizes, int n_in,
                              void* d_out, int out_size) {
    const float* G        = (const float*)d_in[0];
    const float* x_seq    = (const float*)d_in[1];
    const float* init_h   = (const float*)d_in[2];
    const float* W_gate   = (const float*)d_in[3];
    const float* b_gate   = (const float*)d_in[4];
    const float* W_update = (const float*)d_in[5];
    const float* b_update = (const float*)d_in[6];
    float* out = (float*)d_out;

    cudaFuncSetAttribute(encoder_persistent,
                         cudaFuncAttributeMaxDynamicSharedMemorySize, SMEM_PK);

    encoder_persistent<<<NCTA, NTHR, SMEM_PK>>>(
        G, x_seq, init_h, W_gate, b_gate, W_update, b_update, out);
}

// round 16
// speedup vs baseline: 2.0340x; 1.3590x over previous
#include <cuda_runtime.h>
#include <cuda_fp16.h>
#include <cstdint>
#include <math.h>

// Problem constants
#define Bq 32
#define Tq 12
#define Nq 512
#define Cq 2
#define Hq 64
#define Kq 3
#define Pq 66            // C + H
#define NCOLS (Bq*Pq)    // 2112
#define KP  (Kq*Pq)      // 198
#define KS2 208          // sup row stride in fp16
#define OUTG (2*Hq)      // 128
#define NROWS (Bq*Nq)    // 16384
#define NCTA 132
#define NTHR 512

// ---------------- device state ----------------
__device__ float g_h[Bq*Nq*Hq];
__device__ float g_z[Bq*Nq*Hq];
__device__ __half g_g[Kq*Nq*Nq];          // G fp16 [k][n][j]
__device__ __half g_ct[NCOLS*Nq];         // Combined^T fp16 [col][j]
__device__ __half g_sup[NROWS*KS2];       // sup fp16 (pad cols stay 0)
__device__ __half g_Wtg[OUTG*KS2];        // W_gate^T fp16 [o][k], zero-padded
__device__ __half g_Wtu[Hq*KS2];
__device__ unsigned g_bcnt;
__device__ unsigned g_bflag;

// ---------------- helpers ----------------
__device__ __forceinline__ void ldm_x4(uint32_t* r, uint32_t addr) {
    asm volatile("ldmatrix.sync.aligned.m8n8.x4.shared.b16 {%0,%1,%2,%3}, [%4];"
                 : "=r"(r[0]), "=r"(r[1]), "=r"(r[2]), "=r"(r[3]) : "r"(addr));
}
__device__ __forceinline__ void mma_fp16(float* c, const uint32_t* a, const uint32_t* b) {
    asm volatile("mma.sync.aligned.m16n8k16.row.col.f32.f16.f16.f32 "
                 "{%0,%1,%2,%3}, {%4,%5,%6,%7}, {%8,%9}, {%0,%1,%2,%3};"
                 : "+f"(c[0]), "+f"(c[1]), "+f"(c[2]), "+f"(c[3])
                 : "r"(a[0]), "r"(a[1]), "r"(a[2]), "r"(a[3]), "r"(b[0]), "r"(b[1]));
}
__device__ __forceinline__ uint32_t smem_u32(const void* p) {
    uint32_t a;
    asm("{ .reg .u64 t; cvta.to.shared.u64 t, %1; cvt.u32.u64 %0, t; }" : "=r"(a) : "l"(p));
    return a;
}
__device__ __forceinline__ void cp16(uint32_t dst, const void* src) {
    asm volatile("cp.async.cg.shared.global [%0], [%1], 16;" :: "r"(dst), "l"(src));
}
#define CP_COMMIT() asm volatile("cp.async.commit_group;" ::: "memory")
#define CP_WAIT1()  asm volatile("cp.async.wait_group 1;" ::: "memory")
#define CP_WAIT0()  asm volatile("cp.async.wait_group 0;" ::: "memory")

// Sense-reversal grid barrier (all NCTA CTAs resident; every CTA participates).
__device__ __forceinline__ void grid_sync(unsigned &sense) {
    __syncthreads();
    if (threadIdx.x == 0) {
        unsigned target = sense ^ 1u;
        __threadfence();
        unsigned old = atomicAdd(&g_bcnt, 1u);
        if (old == NCTA - 1) {
            atomicExch(&g_bcnt, 0u);
            __threadfence();
            *((volatile unsigned*)&g_bflag) = target;
        } else {
            while (*((volatile unsigned*)&g_bflag) != target) __nanosleep(64);
        }
        __threadfence();
    }
    __syncthreads();
    sense ^= 1u;
}

// ---------------------------------------------------------------------------
// GEMM1 phase: Sup = G[k] @ Comb, SINGLE-pass fp16.
// CTA tile 128x192, 512 threads (16 warps = 4M x 4N, warp tile 32x48).
// 3-stage cp.async pipeline, k-chunk 32, one syncthreads per chunk.
// Job map: cta -> (kk, bm, bn), 132 = 3*4*11.
// ---------------------------------------------------------------------------
#define ROWB 80
#define S1_A 0
#define S1_B 10240            // 128*80
#define STG1 25600            // + 192*80
#define SMEM_PK 98816         // >= max(3*STG1=76800, epilogue 128*193*4=98816)

__device__ __noinline__ void gemm1_phase(char* smg, int cta, int tid) {
    const int kk  = cta / 44;
    const int rem = cta - kk*44;
    const int bm  = rem / 11;
    const int bn  = rem - bm*11;
    const int wid  = tid >> 5;
    const int lane = tid & 31;
    const int wm = wid & 3;
    const int wn = wid >> 2;
    const uint32_t sm0 = smem_u32(smg);

    const __half* A0 = g_g + kk*Nq*Nq + bm*128*Nq;
    const __half* B0 = g_ct + bn*192*Nq;

    const int rS = tid >> 2, qS = tid & 3;        // rows 0..127
    const int rB2 = (tid + 512) >> 2;             // B rows 128..191 (tid<256)

    float acc[2][6][4];
    #pragma unroll
    for (int i = 0; i < 2; i++)
        #pragma unroll
        for (int j = 0; j < 6; j++)
            #pragma unroll
            for (int r = 0; r < 4; r++) acc[i][j][r] = 0.0f;

    const uint32_t aOff = (uint32_t)((lane & 15) * ROWB + (lane >> 4) * 16);
    const uint32_t bOff = (uint32_t)(((lane & 7) + ((lane >> 4) << 3)) * ROWB
                                     + (((lane >> 3) & 1) * 16));

    // prefetch chunks 0, 1
    #pragma unroll
    for (int pc = 0; pc < 2; pc++) {
        const uint32_t base = sm0 + pc*STG1;
        const int kt = pc * 32;
        cp16(base + S1_A + rS*ROWB + qS*16, A0 + rS*Nq + kt + qS*8);
        cp16(base + S1_B + rS*ROWB + qS*16, B0 + rS*Nq + kt + qS*8);
        if (tid < 256)
            cp16(base + S1_B + rB2*ROWB + qS*16, B0 + rB2*Nq + kt + qS*8);
        CP_COMMIT();
    }

    for (int c = 0; c < 16; c++) {
        if (c < 15) { CP_WAIT1(); } else { CP_WAIT0(); }
        __syncthreads();

        if (c < 14) {
            const uint32_t base = sm0 + ((c + 2) % 3)*STG1;
            const int kt = (c + 2) * 32;
            cp16(base + S1_A + rS*ROWB + qS*16, A0 + rS*Nq + kt + qS*8);
            cp16(base + S1_B + rS*ROWB + qS*16, B0 + rS*Nq + kt + qS*8);
            if (tid < 256)
                cp16(base + S1_B + rB2*ROWB + qS*16, B0 + rB2*Nq + kt + qS*8);
            CP_COMMIT();
        }

        const uint32_t base = sm0 + (c % 3)*STG1;
        #pragma unroll
        for (int ks = 0; ks < 2; ks++) {
            const uint32_t kByte = (uint32_t)(ks * 32);
            uint32_t fA[2][4], fB[3][4];

            #pragma unroll
            for (int mf = 0; mf < 2; mf++)
                ldm_x4(fA[mf], base + S1_A + (wm*32 + mf*16)*ROWB + aOff + kByte);
            #pragma unroll
            for (int q = 0; q < 3; q++)
                ldm_x4(fB[q], base + S1_B + (wn*48 + q*16)*ROWB + bOff + kByte);
            #pragma unroll
            for (int mf = 0; mf < 2; mf++)
                #pragma unroll
                for (int q = 0; q < 3; q++) {
                    mma_fp16(acc[mf][2*q+0], fA[mf], &fB[q][0]);
                    mma_fp16(acc[mf][2*q+1], fA[mf], &fB[q][2]);
                }
        }
    }
    __syncthreads();   // pipeline buffers dead; reuse smem for epilogue

    float* fs = (float*)smg;   // 128 x 192, stride 193
    const int quad = lane >> 2;
    const int tq   = lane & 3;
    #pragma unroll
    for (int mf = 0; mf < 2; mf++)
        #pragma unroll
        for (int nf = 0; nf < 6; nf++)
            #pragma unroll
            for (int r = 0; r < 4; r++) {
                int m = wm*32 + mf*16 + ((r >> 1) << 3) + quad;
                int c = wn*48 + nf*8 + tq*2 + (r & 1);
                fs[m*193 + c] = acc[mf][nf][r];
            }
    __syncthreads();
    for (int idx = tid; idx < 128*192; idx += NTHR) {
        int row = idx / 192;
        int c   = idx - row*192;
        float v = fs[row*193 + c];
        int col = bn*192 + c;
        int b = col / Pq;
        int p = col - b*Pq;
        g_sup[(b*Nq + bm*128 + row)*KS2 + kk*Pq + p] = __float2half(v);
    }
}

// ---------------------------------------------------------------------------
// GEMM2 phase: sup @ W, SINGLE-pass fp16, 512 threads (16 warps = 8M x 2N).
// Warp tile 16 x (OUT/2). Only CTAs < 128 call this.
// ---------------------------------------------------------------------------
#define RB2 48

template<int OUT, bool GATE>
__device__ __noinline__ void gemm2_phase(char* smg, int cta, int tid,
                                         const float* __restrict__ bias,
                                         float* __restrict__ out,
                                         const float* __restrict__ x_seq,
                                         int t, int is_last) {
    constexpr int NT  = OUT/2;         // 64 or 32
    constexpr int QF  = NT/16;         // 4 or 2
    constexpr int NF8 = NT/8;          // 8 or 4
    constexpr int OFF2_W = 128*RB2;               // 6144
    constexpr int STG2   = 128*RB2 + OUT*RB2;
    constexpr int SW     = OUT + 1;

    const int bm = cta;
    const int wid  = tid >> 5;
    const int lane = tid & 31;
    const int wm = wid & 7;
    const int wn = wid >> 3;
    const uint32_t sm0 = smem_u32(smg);

    const __half* Wt = GATE ? g_Wtg : g_Wtu;
    const __half* A0 = g_sup + (size_t)bm*128*KS2;

    const int rA = (tid & 255) >> 1, hA = tid & 1;
    const int qW = tid - 256;                     // W ops: tid 256..256+OUT*2

    float acc[NF8][4];
    #pragma unroll
    for (int nf = 0; nf < NF8; nf++)
        #pragma unroll
        for (int r = 0; r < 4; r++)
            acc[nf][r] = bias[wn*NT + nf*8 + (lane & 3)*2 + (r & 1)];

    const uint32_t aOff = (uint32_t)((lane & 15) * RB2 + (lane >> 4) * 16);
    const uint32_t bOff = (uint32_t)(((lane & 7) + ((lane >> 4) << 3)) * RB2
                                     + (((lane >> 3) & 1) * 16));

    {   // prefetch chunk 0
        const uint32_t base = sm0;
        if (tid < 256) cp16(base + 0 + rA*RB2 + hA*16, A0 + rA*KS2 + hA*8);
        else if (qW < OUT*2) {
            int rw = qW >> 1, hw = qW & 1;
            cp16(base + OFF2_W + rw*RB2 + hw*16, Wt + rw*KS2 + hw*8);
        }
        CP_COMMIT();
    }

    for (int c = 0; c < 13; c++) {
        if (c < 12) {
            const uint32_t base = sm0 + ((c + 1) & 1) * STG2;
            const int kt = (c + 1) * 16;
            if (tid < 256) cp16(base + 0 + rA*RB2 + hA*16, A0 + rA*KS2 + kt + hA*8);
            else if (qW < OUT*2) {
                int rw = qW >> 1, hw = qW & 1;
                cp16(base + OFF2_W + rw*RB2 + hw*16, Wt + rw*KS2 + kt + hw*8);
            }
            CP_COMMIT();
            CP_WAIT1();
        } else {
            CP_WAIT0();
        }
        __syncthreads();

        const uint32_t base = sm0 + (c & 1) * STG2;
        uint32_t fA[4], fW[QF][4];

        ldm_x4(fA, base + 0 + (wm*16)*RB2 + aOff);
        #pragma unroll
        for (int q = 0; q < QF; q++)
            ldm_x4(fW[q], base + OFF2_W + (wn*NT + q*16)*RB2 + bOff);
        #pragma unroll
        for (int q = 0; q < QF; q++) {
            mma_fp16(acc[2*q+0], fA, &fW[q][0]);
            mma_fp16(acc[2*q+1], fA, &fW[q][2]);
        }
        __syncthreads();
    }

    // Epilogue: stage fp32 [128][SW], coalesced passes
    float* fs = (float*)smg;
    const int quad = lane >> 2;
    const int tq   = lane & 3;
    #pragma unroll
    for (int nf = 0; nf < NF8; nf++)
        #pragma unroll
        for (int r = 0; r < 4; r++) {
            int rl = wm*16 + ((r >> 1) << 3) + quad;
            int o  = wn*NT + nf*8 + tq*2 + (r & 1);
            fs[rl*SW + o] = acc[nf][r];
        }
    __syncthreads();

    if (GATE) {
        for (int idx = tid; idx < 128*OUT; idx += NTHR) {
            int rl = idx >> 7;
            int o  = idx & 127;
            int row = bm*128 + rl;
            float zv = 1.0f / (1.0f + __expf(-fs[rl*SW + o]));
            if (o < Hq) {
                g_z[row*Hq + o] = zv;
            } else {
                fs[rl*SW + o] = zv * g_h[row*Hq + (o - Hq)];
            }
        }
        __syncthreads();
        for (int idx = tid; idx < Hq*128; idx += NTHR) {
            int hid = idx >> 7;
            int rl  = idx & 127;
            int row = bm*128 + rl;
            int b = row >> 9;
            int n = row & (Nq - 1);
            g_ct[(b*Pq + Cq + hid)*Nq + n] = __float2half(fs[rl*SW + Hq + hid]);
        }
    } else {
        for (int idx = tid; idx < 128*OUT; idx += NTHR) {
            int rl = idx >> 6;
            int o  = idx & 63;
            int row = bm*128 + rl;
            float hc   = tanhf(fs[rl*SW + o]);
            float zv   = g_z[row*Hq + o];
            float hold = g_h[row*Hq + o];
            float hnew = (1.0f - zv)*hold + zv*hc;
            g_h[row*Hq + o] = hnew;
            if (is_last) out[row*Hq + o] = hnew;
            fs[rl*SW + o] = hnew;
        }
        __syncthreads();
        for (int idx = tid; idx < Hq*128; idx += NTHR) {
            int o  = idx >> 7;
            int rl = idx & 127;
            int row = bm*128 + rl;
            int b = row >> 9;
            int n = row & (Nq - 1);
            g_ct[(b*Pq + Cq + o)*Nq + n] = __float2half(fs[rl*SW + o]);
        }
        if (!is_last && tid < 256) {   // fused set_x for t+1
            int p  = tid >> 7;
            int rl = tid & 127;
            int row = bm*128 + rl;
            int b = row >> 9;
            int n = row & (Nq - 1);
            g_ct[(b*Pq + p)*Nq + n] =
                __float2half(x_seq[((b*Tq + (t + 1))*Nq + n)*Cq + p]);
        }
    }
}

// ---------------------------------------------------------------------------
// Persistent kernel: init + 12 steps x 4 phases, grid-synced.
// ---------------------------------------------------------------------------
__global__ void __launch_bounds__(NTHR, 1) encoder_persistent(
    const float* __restrict__ G, const float* __restrict__ x_seq,
    const float* __restrict__ init_h,
    const float* __restrict__ Wg, const float* __restrict__ bg,
    const float* __restrict__ Wu, const float* __restrict__ bu,
    float* __restrict__ out) {
    extern __shared__ char smg[];
    const int cta = blockIdx.x;
    const int tid = threadIdx.x;
    unsigned sense = *((volatile unsigned*)&g_bflag);

    // ---- init phase ----
    const int gs = cta*NTHR + tid;
    const int gstr = NCTA*NTHR;
    for (int idx = gs; idx < Kq*Nq*Nq; idx += gstr)
        g_g[idx] = __float2half(G[idx]);
    for (int idx = gs; idx < (OUTG + Hq)*KS2; idx += gstr) {
        if (idx < OUTG*KS2) {
            int o = idx / KS2, k = idx % KS2;
            g_Wtg[idx] = __float2half((k < KP) ? Wg[k*OUTG + o] : 0.0f);
        } else {
            int q = idx - OUTG*KS2;
            int o = q / KS2, k = q % KS2;
            g_Wtu[q] = __float2half((k < KP) ? Wu[k*Hq + o] : 0.0f);
        }
    }
    for (int idx = gs; idx < Bq*Nq*Hq; idx += gstr) {
        float v = init_h[idx];
        g_h[idx] = v;
        int hid = idx % Hq;
        int row = idx / Hq;
        int b = row / Nq;
        int n = row % Nq;
        g_ct[(b*Pq + Cq + hid)*Nq + n] = __float2half(v);
    }
    for (int idx = gs; idx < Bq*Nq*Cq; idx += gstr) {
        int p = idx % Cq;
        int rest = idx / Cq;
        int n = rest % Nq;
        int b = rest / Nq;
        g_ct[(b*Pq + p)*Nq + n] = __float2half(x_seq[((b*Tq + 0)*Nq + n)*Cq + p]);
    }
    grid_sync(sense);

    for (int t = 0; t < Tq; t++) {
        gemm1_phase(smg, cta, tid);
        grid_sync(sense);
        if (cta < 128) gemm2_phase<OUTG, true>(smg, cta, tid, bg, out, x_seq, t, 0);
        grid_sync(sense);
        gemm1_phase(smg, cta, tid);
        grid_sync(sense);
        if (cta < 128) gemm2_phase<Hq, false>(smg, cta, tid, bu, out, x_seq, t, t == Tq - 1);
        grid_sync(sense);
    }
}

// ---------------------------------------------------------------------------
// kernel_launch
// Inputs: G, x_seq, init_h, W_gate, b_gate, W_update, b_update
// ---------------------------------------------------------------------------
extern "C" void kernel_launch(void* const* d_in, const int* in_sizes, int n_in,
                              void* d_out, int out_size) {
    const float* G        = (const float*)d_in[0];
    const float* x_seq    = (const float*)d_in[1];
    const float* init_h   = (const float*)d_in[2];
    const float* W_gate   = (const float*)d_in[3];
    const float* b_gate   = (const float*)d_in[4];
    const float* W_update = (const float*)d_in[5];
    const float* b_update = (const float*)d_in[6];
    float* out = (float*)d_out;

    cudaFuncSetAttribute(encoder_persistent,
                         cudaFuncAttributeMaxDynamicSharedMemorySize, SMEM_PK);

    encoder_persistent<<<NCTA, NTHR, SMEM_PK>>>(
        G, x_seq, init_h, W_gate, b_gate, W_update, b_update, out);
}

// round 17
// speedup vs baseline: 2.0889x; 1.0270x over previous
#include <cuda_runtime.h>
#include <cuda_fp16.h>
#include <cstdint>
#include <math.h>

// Problem constants
#define Bq 32
#define Tq 12
#define Nq 512
#define Cq 2
#define Hq 64
#define Kq 3
#define Pq 66            // C + H
#define NCOLS (Bq*Pq)    // 2112
#define KP  (Kq*Pq)      // 198
#define KS2 208          // sup row stride in fp16
#define OUTG (2*Hq)      // 128
#define NROWS (Bq*Nq)    // 16384
#define NCTA 132
#define NTHR 512

// ---------------- device state ----------------
__device__ float g_h[Bq*Nq*Hq];
__device__ float g_z[Bq*Nq*Hq];
__device__ __half g_g[Kq*Nq*Nq];          // G fp16 [k][n][j]
__device__ __half g_ct[NCOLS*Nq];         // Combined^T fp16 [col][j]
__device__ __half g_sup[NROWS*KS2];       // sup fp16 (pad cols stay 0)
__device__ __half g_Wtg[OUTG*KS2];        // W_gate^T fp16 [o][k], zero-padded
__device__ __half g_Wtu[Hq*KS2];
__device__ unsigned g_bcnt;
__device__ unsigned g_bflag;

// ---------------- helpers ----------------
__device__ __forceinline__ void ldm_x4(uint32_t* r, uint32_t addr) {
    asm volatile("ldmatrix.sync.aligned.m8n8.x4.shared.b16 {%0,%1,%2,%3}, [%4];"
                 : "=r"(r[0]), "=r"(r[1]), "=r"(r[2]), "=r"(r[3]) : "r"(addr));
}
__device__ __forceinline__ void mma_fp16(float* c, const uint32_t* a, const uint32_t* b) {
    asm volatile("mma.sync.aligned.m16n8k16.row.col.f32.f16.f16.f32 "
                 "{%0,%1,%2,%3}, {%4,%5,%6,%7}, {%8,%9}, {%0,%1,%2,%3};"
                 : "+f"(c[0]), "+f"(c[1]), "+f"(c[2]), "+f"(c[3])
                 : "r"(a[0]), "r"(a[1]), "r"(a[2]), "r"(a[3]), "r"(b[0]), "r"(b[1]));
}
__device__ __forceinline__ uint32_t smem_u32(const void* p) {
    uint32_t a;
    asm("{ .reg .u64 t; cvta.to.shared.u64 t, %1; cvt.u32.u64 %0, t; }" : "=r"(a) : "l"(p));
    return a;
}
__device__ __forceinline__ void cp16(uint32_t dst, const void* src) {
    asm volatile("cp.async.cg.shared.global [%0], [%1], 16;" :: "r"(dst), "l"(src));
}
#define CP_COMMIT() asm volatile("cp.async.commit_group;" ::: "memory")
#define CP_WAIT1()  asm volatile("cp.async.wait_group 1;" ::: "memory")
#define CP_WAIT0()  asm volatile("cp.async.wait_group 0;" ::: "memory")

// Sense-reversal grid barrier (all NCTA CTAs resident; every CTA participates).
__device__ __forceinline__ void grid_sync(unsigned &sense) {
    __syncthreads();
    if (threadIdx.x == 0) {
        unsigned target = sense ^ 1u;
        __threadfence();
        unsigned old = atomicAdd(&g_bcnt, 1u);
        if (old == NCTA - 1) {
            atomicExch(&g_bcnt, 0u);
            __threadfence();
            *((volatile unsigned*)&g_bflag) = target;
        } else {
            while (*((volatile unsigned*)&g_bflag) != target) __nanosleep(64);
        }
        __threadfence();
    }
    __syncthreads();
    sense ^= 1u;
}

// ---------------------------------------------------------------------------
// GEMM1 phase: Sup = G[k] @ Comb, SINGLE-pass fp16.
// CTA tile 128x192, 512 threads (16 warps = 4M x 4N, warp tile 32x48).
// 3-stage cp.async pipeline, k-chunk 32, one syncthreads per chunk.
// Job map: cta -> (kk, bm, bn), 132 = 3*4*11.
// ---------------------------------------------------------------------------
#define ROWB 80
#define S1_A 0
#define S1_B 10240            // 128*80
#define STG1 25600            // + 192*80
#define SMEM_PK 110592        // max(3*STG1=76800, gemm1 epi 98816, gemm2 2*55296)

__device__ __noinline__ void gemm1_phase(char* smg, int cta, int tid) {
    const int kk  = cta / 44;
    const int rem = cta - kk*44;
    const int bm  = rem / 11;
    const int bn  = rem - bm*11;
    const int wid  = tid >> 5;
    const int lane = tid & 31;
    const int wm = wid & 3;
    const int wn = wid >> 2;
    const uint32_t sm0 = smem_u32(smg);

    const __half* A0 = g_g + kk*Nq*Nq + bm*128*Nq;
    const __half* B0 = g_ct + bn*192*Nq;

    const int rS = tid >> 2, qS = tid & 3;        // rows 0..127
    const int rB2 = (tid + 512) >> 2;             // B rows 128..191 (tid<256)

    float acc[2][6][4];
    #pragma unroll
    for (int i = 0; i < 2; i++)
        #pragma unroll
        for (int j = 0; j < 6; j++)
            #pragma unroll
            for (int r = 0; r < 4; r++) acc[i][j][r] = 0.0f;

    const uint32_t aOff = (uint32_t)((lane & 15) * ROWB + (lane >> 4) * 16);
    const uint32_t bOff = (uint32_t)(((lane & 7) + ((lane >> 4) << 3)) * ROWB
                                     + (((lane >> 3) & 1) * 16));

    // prefetch chunks 0, 1
    #pragma unroll
    for (int pc = 0; pc < 2; pc++) {
        const uint32_t base = sm0 + pc*STG1;
        const int kt = pc * 32;
        cp16(base + S1_A + rS*ROWB + qS*16, A0 + rS*Nq + kt + qS*8);
        cp16(base + S1_B + rS*ROWB + qS*16, B0 + rS*Nq + kt + qS*8);
        if (tid < 256)
            cp16(base + S1_B + rB2*ROWB + qS*16, B0 + rB2*Nq + kt + qS*8);
        CP_COMMIT();
    }

    for (int c = 0; c < 16; c++) {
        if (c < 15) { CP_WAIT1(); } else { CP_WAIT0(); }
        __syncthreads();

        if (c < 14) {
            const uint32_t base = sm0 + ((c + 2) % 3)*STG1;
            const int kt = (c + 2) * 32;
            cp16(base + S1_A + rS*ROWB + qS*16, A0 + rS*Nq + kt + qS*8);
            cp16(base + S1_B + rS*ROWB + qS*16, B0 + rS*Nq + kt + qS*8);
            if (tid < 256)
                cp16(base + S1_B + rB2*ROWB + qS*16, B0 + rB2*Nq + kt + qS*8);
            CP_COMMIT();
        }

        const uint32_t base = sm0 + (c % 3)*STG1;
        #pragma unroll
        for (int ks = 0; ks < 2; ks++) {
            const uint32_t kByte = (uint32_t)(ks * 32);
            uint32_t fA[2][4], fB[3][4];

            #pragma unroll
            for (int mf = 0; mf < 2; mf++)
                ldm_x4(fA[mf], base + S1_A + (wm*32 + mf*16)*ROWB + aOff + kByte);
            #pragma unroll
            for (int q = 0; q < 3; q++)
                ldm_x4(fB[q], base + S1_B + (wn*48 + q*16)*ROWB + bOff + kByte);
            #pragma unroll
            for (int mf = 0; mf < 2; mf++)
                #pragma unroll
                for (int q = 0; q < 3; q++) {
                    mma_fp16(acc[mf][2*q+0], fA[mf], &fB[q][0]);
                    mma_fp16(acc[mf][2*q+1], fA[mf], &fB[q][2]);
                }
        }
    }
    __syncthreads();   // pipeline buffers dead; reuse smem for epilogue

    float* fs = (float*)smg;   // 128 x 192, stride 193
    const int quad = lane >> 2;
    const int tq   = lane & 3;
    #pragma unroll
    for (int mf = 0; mf < 2; mf++)
        #pragma unroll
        for (int nf = 0; nf < 6; nf++)
            #pragma unroll
            for (int r = 0; r < 4; r++) {
                int m = wm*32 + mf*16 + ((r >> 1) << 3) + quad;
                int c = wn*48 + nf*8 + tq*2 + (r & 1);
                fs[m*193 + c] = acc[mf][nf][r];
            }
    __syncthreads();
    for (int idx = tid; idx < 128*192; idx += NTHR) {
        int row = idx / 192;
        int c   = idx - row*192;
        float v = fs[row*193 + c];
        int col = bn*192 + c;
        int b = col / Pq;
        int p = col - b*Pq;
        g_sup[(b*Nq + bm*128 + row)*KS2 + kk*Pq + p] = __float2half(v);
    }
}

// ---------------------------------------------------------------------------
// GEMM2 phase: sup @ W, SINGLE-pass fp16, single-shot smem (no inner syncs).
// A (128 x 208) and W (OUT x 208) fully resident, row stride 432 B
// (432 = 27*16 aligned; 432 mod 128 = 48 -> ldmatrix conflict-free).
// 512 threads, 16 warps = 8M x 2N, warp tile 16 x (OUT/2). CTAs < 128 only.
// ---------------------------------------------------------------------------
#define RBS 432
#define SEGS 26              // 208 fp16 = 416 B = 26 x 16 B per row

template<int OUT, bool GATE>
__device__ __noinline__ void gemm2_phase(char* smg, int cta, int tid,
                                         const float* __restrict__ bias,
                                         float* __restrict__ out,
                                         const float* __restrict__ x_seq,
                                         int t, int is_last) {
    constexpr int NT  = OUT/2;         // 64 or 32
    constexpr int QF  = NT/16;         // 4 or 2
    constexpr int NF8 = NT/8;          // 8 or 4
    constexpr int OFFW = 128*RBS;      // 55296
    constexpr int SW   = OUT + 1;

    const int bm = cta;
    const int wid  = tid >> 5;
    const int lane = tid & 31;
    const int wm = wid & 7;
    const int wn = wid >> 3;
    const uint32_t sm0 = smem_u32(smg);

    const __half* Wt = GATE ? g_Wtg : g_Wtu;
    const __half* A0 = g_sup + (size_t)bm*128*KS2;

    float acc[NF8][4];
    #pragma unroll
    for (int nf = 0; nf < NF8; nf++)
        #pragma unroll
        for (int r = 0; r < 4; r++)
            acc[nf][r] = bias[wn*NT + nf*8 + (lane & 3)*2 + (r & 1)];

    // ---- single-shot load: A (128*SEGS ops) + W (OUT*SEGS ops), one group
    for (int idx = tid; idx < 128*SEGS; idx += NTHR) {
        int row = idx / SEGS, seg = idx - row*SEGS;
        cp16(sm0 + row*RBS + seg*16, A0 + row*KS2 + seg*8);
    }
    for (int idx = tid; idx < OUT*SEGS; idx += NTHR) {
        int row = idx / SEGS, seg = idx - row*SEGS;
        cp16(sm0 + OFFW + row*RBS + seg*16, Wt + row*KS2 + seg*8);
    }
    CP_COMMIT();
    CP_WAIT0();
    __syncthreads();

    const uint32_t aOff = (uint32_t)((lane & 15) * RBS + (lane >> 4) * 16);
    const uint32_t bOff = (uint32_t)(((lane & 7) + ((lane >> 4) << 3)) * RBS
                                     + (((lane >> 3) & 1) * 16));

    // ---- 13 k16 steps, zero syncs
    #pragma unroll
    for (int c = 0; c < 13; c++) {
        const uint32_t kByte = (uint32_t)(c * 32);
        uint32_t fA[4], fW[QF][4];

        ldm_x4(fA, sm0 + (wm*16)*RBS + aOff + kByte);
        #pragma unroll
        for (int q = 0; q < QF; q++)
            ldm_x4(fW[q], sm0 + OFFW + (wn*NT + q*16)*RBS + bOff + kByte);
        #pragma unroll
        for (int q = 0; q < QF; q++) {
            mma_fp16(acc[2*q+0], fA, &fW[q][0]);
            mma_fp16(acc[2*q+1], fA, &fW[q][2]);
        }
    }
    __syncthreads();   // smem A/W dead; reuse for epilogue staging

    // Epilogue: stage fp32 [128][SW], coalesced passes
    float* fs = (float*)smg;
    const int quad = lane >> 2;
    const int tq   = lane & 3;
    #pragma unroll
    for (int nf = 0; nf < NF8; nf++)
        #pragma unroll
        for (int r = 0; r < 4; r++) {
            int rl = wm*16 + ((r >> 1) << 3) + quad;
            int o  = wn*NT + nf*8 + tq*2 + (r & 1);
            fs[rl*SW + o] = acc[nf][r];
        }
    __syncthreads();

    if (GATE) {
        for (int idx = tid; idx < 128*OUT; idx += NTHR) {
            int rl = idx >> 7;
            int o  = idx & 127;
            int row = bm*128 + rl;
            float zv = 1.0f / (1.0f + __expf(-fs[rl*SW + o]));
            if (o < Hq) {
                g_z[row*Hq + o] = zv;
            } else {
                fs[rl*SW + o] = zv * g_h[row*Hq + (o - Hq)];
            }
        }
        __syncthreads();
        for (int idx = tid; idx < Hq*128; idx += NTHR) {
            int hid = idx >> 7;
            int rl  = idx & 127;
            int row = bm*128 + rl;
            int b = row >> 9;
            int n = row & (Nq - 1);
            g_ct[(b*Pq + Cq + hid)*Nq + n] = __float2half(fs[rl*SW + Hq + hid]);
        }
    } else {
        for (int idx = tid; idx < 128*OUT; idx += NTHR) {
            int rl = idx >> 6;
            int o  = idx & 63;
            int row = bm*128 + rl;
            float hc   = tanhf(fs[rl*SW + o]);
            float zv   = g_z[row*Hq + o];
            float hold = g_h[row*Hq + o];
            float hnew = (1.0f - zv)*hold + zv*hc;
            g_h[row*Hq + o] = hnew;
            if (is_last) out[row*Hq + o] = hnew;
            fs[rl*SW + o] = hnew;
        }
        __syncthreads();
        for (int idx = tid; idx < Hq*128; idx += NTHR) {
            int o  = idx >> 7;
            int rl = idx & 127;
            int row = bm*128 + rl;
            int b = row >> 9;
            int n = row & (Nq - 1);
            g_ct[(b*Pq + Cq + o)*Nq + n] = __float2half(fs[rl*SW + o]);
        }
        if (!is_last && tid < 256) {   // fused set_x for t+1
            int p  = tid >> 7;
            int rl = tid & 127;
            int row = bm*128 + rl;
            int b = row >> 9;
            int n = row & (Nq - 1);
            g_ct[(b*Pq + p)*Nq + n] =
                __float2half(x_seq[((b*Tq + (t + 1))*Nq + n)*Cq + p]);
        }
    }
}

// ---------------------------------------------------------------------------
// Persistent kernel: init + 12 steps x 4 phases, grid-synced.
// ---------------------------------------------------------------------------
__global__ void __launch_bounds__(NTHR, 1) encoder_persistent(
    const float* __restrict__ G, const float* __restrict__ x_seq,
    const float* __restrict__ init_h,
    const float* __restrict__ Wg, const float* __restrict__ bg,
    const float* __restrict__ Wu, const float* __restrict__ bu,
    float* __restrict__ out) {
    extern __shared__ char smg[];
    const int cta = blockIdx.x;
    const int tid = threadIdx.x;
    unsigned sense = *((volatile unsigned*)&g_bflag);

    // ---- init phase ----
    const int gs = cta*NTHR + tid;
    const int gstr = NCTA*NTHR;
    for (int idx = gs; idx < Kq*Nq*Nq; idx += gstr)
        g_g[idx] = __float2half(G[idx]);
    for (int idx = gs; idx < (OUTG + Hq)*KS2; idx += gstr) {
        if (idx < OUTG*KS2) {
            int o = idx / KS2, k = idx % KS2;
            g_Wtg[idx] = __float2half((k < KP) ? Wg[k*OUTG + o] : 0.0f);
        } else {
            int q = idx - OUTG*KS2;
            int o = q / KS2, k = q % KS2;
            g_Wtu[q] = __float2half((k < KP) ? Wu[k*Hq + o] : 0.0f);
        }
    }
    for (int idx = gs; idx < Bq*Nq*Hq; idx += gstr) {
        float v = init_h[idx];
        g_h[idx] = v;
        int hid = idx % Hq;
        int row = idx / Hq;
        int b = row / Nq;
        int n = row % Nq;
        g_ct[(b*Pq + Cq + hid)*Nq + n] = __float2half(v);
    }
    for (int idx = gs; idx < Bq*Nq*Cq; idx += gstr) {
        int p = idx % Cq;
        int rest = idx / Cq;
        int n = rest % Nq;
        int b = rest / Nq;
        g_ct[(b*Pq + p)*Nq + n] = __float2half(x_seq[((b*Tq + 0)*Nq + n)*Cq + p]);
    }
    grid_sync(sense);

    for (int t = 0; t < Tq; t++) {
        gemm1_phase(smg, cta, tid);
        grid_sync(sense);
        if (cta < 128) gemm2_phase<OUTG, true>(smg, cta, tid, bg, out, x_seq, t, 0);
        grid_sync(sense);
        gemm1_phase(smg, cta, tid);
        grid_sync(sense);
        if (cta < 128) gemm2_phase<Hq, false>(smg, cta, tid, bu, out, x_seq, t, t == Tq - 1);
        grid_sync(sense);
    }
}

// ---------------------------------------------------------------------------
// kernel_launch
// Inputs: G, x_seq, init_h, W_gate, b_gate, W_update, b_update
// ---------------------------------------------------------------------------
extern "C" void kernel_launch(void* const* d_in, const int* in_sizes, int n_in,
                              void* d_out, int out_size) {
    const float* G        = (const float*)d_in[0];
    const float* x_seq    = (const float*)d_in[1];
    const float* init_h   = (const float*)d_in[2];
    const float* W_gate   = (const float*)d_in[3];
    const float* b_gate   = (const float*)d_in[4];
    const float* W_update = (const float*)d_in[5];
    const float* b_update = (const float*)d_in[6];
    float* out = (float*)d_out;

    cudaFuncSetAttribute(encoder_persistent,
                         cudaFuncAttributeMaxDynamicSharedMemorySize, SMEM_PK);

    encoder_persistent<<<NCTA, NTHR, SMEM_PK>>>(
        G, x_seq, init_h, W_gate, b_gate, W_update, b_update, out);
}